// round 1
// baseline (speedup 1.0000x reference)
#include <cuda_runtime.h>
#include <math.h>

#define D_MODEL 4096
#define HEAD 128
#define SEQ 4096
#define BATCH 2

// Scratch (allocation-free rule: static __device__ arrays)
__device__ float g_q[BATCH * SEQ * HEAD];
__device__ float g_k[BATCH * SEQ * HEAD];
__device__ float g_v[BATCH * SEQ * HEAD];

// ---------------------------------------------------------------------------
// Kernel 1: fused QKV projection + RoPE.
// grid = (SEQ/64, BATCH, 3 {q,k,v}), block = 256.
// Each CTA computes a [64 x 128] tile of one projection: C = Xtile * W^T.
// Thread micro-tile 4x8 (thread grid 16x16).
// ---------------------------------------------------------------------------
__global__ __launch_bounds__(256) void proj_rope_kernel(
    const float* __restrict__ x, const float* __restrict__ Wq,
    const float* __restrict__ Wk, const float* __restrict__ Wv)
{
    __shared__ __align__(16) float xsT[32][68];    // k-major x tile (64 rows)
    __shared__ __align__(16) float wsT[32][132];   // k-major W tile (128 rows)

    const int rt = blockIdx.x;
    const int b  = blockIdx.y;
    const int mz = blockIdx.z;
    const float* __restrict__ W = (mz == 0) ? Wq : (mz == 1) ? Wk : Wv;
    float* __restrict__ dst = (mz == 0) ? g_q : (mz == 1) ? g_k : g_v;

    const int tid = threadIdx.x;
    const int ty = tid >> 4;   // m group (4 rows each)
    const int tx = tid & 15;   // n group (8 cols each)

    const float* __restrict__ xrow = x + ((size_t)b * SEQ + (size_t)rt * 64) * D_MODEL;

    float acc[4][8];
#pragma unroll
    for (int i = 0; i < 4; i++)
#pragma unroll
        for (int j = 0; j < 8; j++) acc[i][j] = 0.f;

    for (int k0 = 0; k0 < D_MODEL; k0 += 32) {
        __syncthreads();
        // load x tile (64 x 32) transposed into smem
#pragma unroll
        for (int i = 0; i < 2; i++) {
            int fidx = i * 256 + tid;
            int r = fidx >> 3, c4 = fidx & 7;
            float4 v = *(const float4*)(xrow + (size_t)r * D_MODEL + k0 + c4 * 4);
            xsT[c4 * 4 + 0][r] = v.x; xsT[c4 * 4 + 1][r] = v.y;
            xsT[c4 * 4 + 2][r] = v.z; xsT[c4 * 4 + 3][r] = v.w;
        }
        // load W tile (128 x 32) transposed into smem
#pragma unroll
        for (int i = 0; i < 4; i++) {
            int fidx = i * 256 + tid;
            int r = fidx >> 3, c4 = fidx & 7;
            float4 v = *(const float4*)(W + (size_t)r * D_MODEL + k0 + c4 * 4);
            wsT[c4 * 4 + 0][r] = v.x; wsT[c4 * 4 + 1][r] = v.y;
            wsT[c4 * 4 + 2][r] = v.z; wsT[c4 * 4 + 3][r] = v.w;
        }
        __syncthreads();
#pragma unroll 8
        for (int kk = 0; kk < 32; kk++) {
            float4 a  = *(const float4*)&xsT[kk][ty * 4];
            float4 b0 = *(const float4*)&wsT[kk][tx * 8];
            float4 b1 = *(const float4*)&wsT[kk][tx * 8 + 4];
            float av[4] = {a.x, a.y, a.z, a.w};
            float bv[8] = {b0.x, b0.y, b0.z, b0.w, b1.x, b1.y, b1.z, b1.w};
#pragma unroll
            for (int i = 0; i < 4; i++)
#pragma unroll
                for (int j = 0; j < 8; j++) acc[i][j] += av[i] * bv[j];
        }
    }

    const int m0 = ty * 4, n0 = tx * 8;

    // RoPE for q and k (mz 0,1). Mimic reference f32 rounding:
    // theta rounded to f32, angle = f32(s) * f32(theta), accurate sincosf.
    if (mz < 2) {
#pragma unroll
        for (int j = 0; j < 4; j++) {
            int p = (n0 >> 1) + j;  // pair index
            float theta = (float)exp(-0.28782313662425574 * (double)p); // ln(10000)/32
#pragma unroll
            for (int i = 0; i < 4; i++) {
                float ang = (float)(rt * 64 + m0 + i) * theta;
                float cs, sn;
                sincosf(ang, &sn, &cs);
                float x0 = acc[i][2 * j], x1 = acc[i][2 * j + 1];
                acc[i][2 * j]     = x0 * cs - x1 * sn;
                acc[i][2 * j + 1] = x1 * cs + x0 * sn;
            }
        }
    }

    float* __restrict__ drow = dst + ((size_t)b * SEQ + (size_t)rt * 64) * HEAD;
#pragma unroll
    for (int i = 0; i < 4; i++) {
        float4 o0 = make_float4(acc[i][0], acc[i][1], acc[i][2], acc[i][3]);
        float4 o1 = make_float4(acc[i][4], acc[i][5], acc[i][6], acc[i][7]);
        *(float4*)&drow[(size_t)(m0 + i) * HEAD + n0]     = o0;
        *(float4*)&drow[(size_t)(m0 + i) * HEAD + n0 + 4] = o1;
    }
}

// ---------------------------------------------------------------------------
// Kernel 2: causal flash attention, fp32.
// grid = (64, BATCH), block = 256. Each CTA processes q-tile pair
// (bx, 127-bx) of 32 rows each -> balanced ~65 k-tiles (64 keys) per CTA.
// ---------------------------------------------------------------------------
#define QST_OFF 0            // [128][34]
#define KST_OFF 4352         // [128][64] (xor-16 swizzled float4 groups)
#define VS_OFF  12544        // [64][132]
#define PST_OFF 20992        // [64][34]
#define ATTN_SMEM_FLOATS 23168
#define ATTN_SMEM_BYTES (ATTN_SMEM_FLOATS * 4)

__global__ __launch_bounds__(256) void attn_kernel(float* __restrict__ out)
{
    extern __shared__ __align__(16) float sm[];
    float* QsT = sm + QST_OFF;
    float* KsT = sm + KST_OFF;
    float* Vs  = sm + VS_OFF;
    float* PsT = sm + PST_OFF;

    const int tid = threadIdx.x;
    const int ty = tid >> 4;   // 0..15 -> 2 q rows each
    const int tx = tid & 15;   // 0..15 -> 4 key cols (phase1) / 8 out cols (phase2)
    const int b = blockIdx.y;
    const float scale = 0.08838834764831845f;  // 1/sqrt(128)

#pragma unroll 1
    for (int half = 0; half < 2; half++) {
        const int qt = half ? (127 - (int)blockIdx.x) : (int)blockIdx.x;
        const int qbase = qt * 32;

        __syncthreads();
        // Load Q tile [32 x 128] transposed, pre-scaled
        const float* __restrict__ qsrc = g_q + ((size_t)b * SEQ + qbase) * HEAD;
#pragma unroll
        for (int i = 0; i < 4; i++) {
            int fidx = i * 256 + tid;
            int r = fidx >> 5, c4 = fidx & 31;
            float4 v = *(const float4*)(qsrc + (size_t)r * HEAD + c4 * 4);
            QsT[(c4 * 4 + 0) * 34 + r] = v.x * scale;
            QsT[(c4 * 4 + 1) * 34 + r] = v.y * scale;
            QsT[(c4 * 4 + 2) * 34 + r] = v.z * scale;
            QsT[(c4 * 4 + 3) * 34 + r] = v.w * scale;
        }

        float m_run[2] = {-INFINITY, -INFINITY};
        float l_run[2] = {0.f, 0.f};
        float o[2][8];
#pragma unroll
        for (int i = 0; i < 2; i++)
#pragma unroll
            for (int j = 0; j < 8; j++) o[i][j] = 0.f;

        const int ntiles = (qbase + 32 + 63) >> 6;
        for (int kt = 0; kt < ntiles; kt++) {
            const int kbase = kt * 64;
            __syncthreads();  // prior phase2 done with Ks/Vs/PsT
            const float* __restrict__ ksrc = g_k + ((size_t)b * SEQ + kbase) * HEAD;
            const float* __restrict__ vsrc = g_v + ((size_t)b * SEQ + kbase) * HEAD;
#pragma unroll
            for (int i = 0; i < 8; i++) {
                int fidx = i * 256 + tid;
                int r = fidx >> 5, c4 = fidx & 31;   // r = key row, c4*4 = head-dim base
                float4 kv = *(const float4*)(ksrc + (size_t)r * HEAD + c4 * 4);
                int k0 = c4 * 4;
                // element (k, key=r): KsT[k*64 + ((r>>2)^(k&15))*4 + (r&3)]
                KsT[(k0 + 0) * 64 + ((((r >> 2) ^ ((k0 + 0) & 15))) << 2) + (r & 3)] = kv.x;
                KsT[(k0 + 1) * 64 + ((((r >> 2) ^ ((k0 + 1) & 15))) << 2) + (r & 3)] = kv.y;
                KsT[(k0 + 2) * 64 + ((((r >> 2) ^ ((k0 + 2) & 15))) << 2) + (r & 3)] = kv.z;
                KsT[(k0 + 3) * 64 + ((((r >> 2) ^ ((k0 + 3) & 15))) << 2) + (r & 3)] = kv.w;
                float4 vv = *(const float4*)(vsrc + (size_t)r * HEAD + c4 * 4);
                *(float4*)&Vs[r * 132 + c4 * 4] = vv;
            }
            __syncthreads();

            // Phase 1: S = Q K^T (scaled), micro 2x4
            float sacc[2][4];
#pragma unroll
            for (int i = 0; i < 2; i++)
#pragma unroll
                for (int j = 0; j < 4; j++) sacc[i][j] = 0.f;

#pragma unroll 8
            for (int k = 0; k < 128; k++) {
                float2 a = *(const float2*)(QsT + k * 34 + ty * 2);
                float4 bq = *(const float4*)(KsT + k * 64 + ((tx ^ (k & 15)) << 2));
                sacc[0][0] += a.x * bq.x; sacc[0][1] += a.x * bq.y;
                sacc[0][2] += a.x * bq.z; sacc[0][3] += a.x * bq.w;
                sacc[1][0] += a.y * bq.x; sacc[1][1] += a.y * bq.y;
                sacc[1][2] += a.y * bq.z; sacc[1][3] += a.y * bq.w;
            }

            // causal mask
#pragma unroll
            for (int i = 0; i < 2; i++) {
                int qrow = qbase + ty * 2 + i;
#pragma unroll
                for (int j = 0; j < 4; j++)
                    if (kbase + tx * 4 + j > qrow) sacc[i][j] = -INFINITY;
            }

            // online softmax per row (row = 16 tx lanes x 4 local cols)
#pragma unroll
            for (int i = 0; i < 2; i++) {
                float mx = fmaxf(fmaxf(sacc[i][0], sacc[i][1]),
                                 fmaxf(sacc[i][2], sacc[i][3]));
#pragma unroll
                for (int off = 8; off >= 1; off >>= 1)
                    mx = fmaxf(mx, __shfl_xor_sync(0xffffffffu, mx, off));
                float mn = fmaxf(m_run[i], mx);
                float alpha = expf(m_run[i] - mn);    // 0 on first tile
                float p0 = expf(sacc[i][0] - mn);
                float p1 = expf(sacc[i][1] - mn);
                float p2 = expf(sacc[i][2] - mn);
                float p3 = expf(sacc[i][3] - mn);
                float rs = (p0 + p1) + (p2 + p3);
#pragma unroll
                for (int off = 8; off >= 1; off >>= 1)
                    rs += __shfl_xor_sync(0xffffffffu, rs, off);
                l_run[i] = l_run[i] * alpha + rs;
                m_run[i] = mn;
#pragma unroll
                for (int j = 0; j < 8; j++) o[i][j] *= alpha;
                PsT[(tx * 4 + 0) * 34 + ty * 2 + i] = p0;
                PsT[(tx * 4 + 1) * 34 + ty * 2 + i] = p1;
                PsT[(tx * 4 + 2) * 34 + ty * 2 + i] = p2;
                PsT[(tx * 4 + 3) * 34 + ty * 2 + i] = p3;
            }
            __syncthreads();

            // Phase 2: O += P V, micro 2x8
#pragma unroll 8
            for (int j = 0; j < 64; j++) {
                float2 a = *(const float2*)(PsT + j * 34 + ty * 2);
                float4 b0 = *(const float4*)(Vs + j * 132 + tx * 8);
                float4 b1 = *(const float4*)(Vs + j * 132 + tx * 8 + 4);
                o[0][0] += a.x * b0.x; o[0][1] += a.x * b0.y;
                o[0][2] += a.x * b0.z; o[0][3] += a.x * b0.w;
                o[0][4] += a.x * b1.x; o[0][5] += a.x * b1.y;
                o[0][6] += a.x * b1.z; o[0][7] += a.x * b1.w;
                o[1][0] += a.y * b0.x; o[1][1] += a.y * b0.y;
                o[1][2] += a.y * b0.z; o[1][3] += a.y * b0.w;
                o[1][4] += a.y * b1.x; o[1][5] += a.y * b1.y;
                o[1][6] += a.y * b1.z; o[1][7] += a.y * b1.w;
            }
        }

        float* __restrict__ orow = out + ((size_t)b * SEQ + qbase) * HEAD;
#pragma unroll
        for (int i = 0; i < 2; i++) {
            float inv = 1.f / l_run[i];
            float4 r0 = make_float4(o[i][0] * inv, o[i][1] * inv,
                                    o[i][2] * inv, o[i][3] * inv);
            float4 r1 = make_float4(o[i][4] * inv, o[i][5] * inv,
                                    o[i][6] * inv, o[i][7] * inv);
            *(float4*)&orow[(size_t)(ty * 2 + i) * HEAD + tx * 8]     = r0;
            *(float4*)&orow[(size_t)(ty * 2 + i) * HEAD + tx * 8 + 4] = r1;
        }
    }
}

extern "C" void kernel_launch(void* const* d_in, const int* in_sizes, int n_in,
                              void* d_out, int out_size)
{
    const float* x  = (const float*)d_in[0];
    const float* Wq = (const float*)d_in[1];
    const float* Wk = (const float*)d_in[2];
    const float* Wv = (const float*)d_in[3];
    float* out = (float*)d_out;

    cudaFuncSetAttribute((const void*)attn_kernel,
                         cudaFuncAttributeMaxDynamicSharedMemorySize,
                         ATTN_SMEM_BYTES);

    proj_rope_kernel<<<dim3(SEQ / 64, BATCH, 3), 256>>>(x, Wq, Wk, Wv);
    attn_kernel<<<dim3(64, BATCH), 256, ATTN_SMEM_BYTES>>>(out);
}

// round 8
// speedup vs baseline: 1.7351x; 1.7351x over previous
#include <cuda_runtime.h>
#include <cuda_bf16.h>
#include <math.h>
#include <stdint.h>

#define D_MODEL 4096
#define HEAD 128
#define SEQ 4096
#define BATCH 2

// Scratch (allocation-free rule: static __device__ arrays)
__device__ float g_q[BATCH * SEQ * HEAD];
__device__ float g_k[BATCH * SEQ * HEAD];
__device__ float g_v[BATCH * SEQ * HEAD];

// bf16 hi/lo split operands
__device__ __align__(16) __nv_bfloat16 g_xh[BATCH * SEQ * D_MODEL];
__device__ __align__(16) __nv_bfloat16 g_xl[BATCH * SEQ * D_MODEL];
__device__ __align__(16) __nv_bfloat16 g_wh[3 * HEAD * D_MODEL];
__device__ __align__(16) __nv_bfloat16 g_wl[3 * HEAD * D_MODEL];

__device__ __forceinline__ uint32_t smem_to_u32(const void* smem_ptr) {
    uint32_t addr;
    asm("{ .reg .u64 tmp; cvta.to.shared.u64 tmp, %1; cvt.u32.u64 %0, tmp; }"
        : "=r"(addr) : "l"(smem_ptr));
    return addr;
}

#define CP_ASYNC16(dst, src) \
    asm volatile("cp.async.cg.shared.global [%0], [%1], 16;" \
                 :: "r"(dst), "l"(src) : "memory")
#define CP_COMMIT asm volatile("cp.async.commit_group;" ::: "memory")
#define CP_WAIT(n) asm volatile("cp.async.wait_group %0;" :: "n"(n) : "memory")

__device__ __forceinline__ void ldm_x4(uint32_t* r, uint32_t addr) {
    asm volatile("ldmatrix.sync.aligned.m8n8.x4.shared.b16 {%0,%1,%2,%3}, [%4];"
                 : "=r"(r[0]), "=r"(r[1]), "=r"(r[2]), "=r"(r[3]) : "r"(addr));
}

__device__ __forceinline__ void mma16816(float* c, const uint32_t* a,
                                         uint32_t b0, uint32_t b1) {
    asm volatile(
        "mma.sync.aligned.m16n8k16.row.col.f32.bf16.bf16.f32 "
        "{%0,%1,%2,%3}, {%4,%5,%6,%7}, {%8,%9}, {%0,%1,%2,%3};"
        : "+f"(c[0]), "+f"(c[1]), "+f"(c[2]), "+f"(c[3])
        : "r"(a[0]), "r"(a[1]), "r"(a[2]), "r"(a[3]), "r"(b0), "r"(b1));
}

// ===========================================================================
// Kernel 0: fp32 -> bf16 hi/lo split conversion for x and Wq/Wk/Wv.
// one float4 per thread.
// ===========================================================================
#define N4X (BATCH * SEQ * D_MODEL / 4)          // 8388608
#define N4W_PER (HEAD * D_MODEL / 4)             // 131072
#define N4TOT (N4X + 3 * N4W_PER)                // 8781824
#define CONV_BLOCKS (N4TOT / 256)                // 34304

__global__ __launch_bounds__(256) void conv_kernel(
    const float* __restrict__ x, const float* __restrict__ Wq,
    const float* __restrict__ Wk, const float* __restrict__ Wv)
{
    size_t i = (size_t)blockIdx.x * 256 + threadIdx.x;
    float4 v;
    __nv_bfloat16 *dh, *dl;
    if (i < N4X) {
        v = ((const float4*)x)[i];
        dh = g_xh + i * 4;
        dl = g_xl + i * 4;
    } else {
        size_t j = i - N4X;
        int mz = (int)(j / N4W_PER);
        size_t wj = j - (size_t)mz * N4W_PER;
        const float* W = (mz == 0) ? Wq : (mz == 1) ? Wk : Wv;
        v = ((const float4*)W)[wj];
        dh = g_wh + ((size_t)mz * N4W_PER + wj) * 4;
        dl = g_wl + ((size_t)mz * N4W_PER + wj) * 4;
    }
    __nv_bfloat162 h01, h23, l01, l23;
    h01.x = __float2bfloat16_rn(v.x); h01.y = __float2bfloat16_rn(v.y);
    h23.x = __float2bfloat16_rn(v.z); h23.y = __float2bfloat16_rn(v.w);
    l01.x = __float2bfloat16_rn(v.x - __bfloat162float(h01.x));
    l01.y = __float2bfloat16_rn(v.y - __bfloat162float(h01.y));
    l23.x = __float2bfloat16_rn(v.z - __bfloat162float(h23.x));
    l23.y = __float2bfloat16_rn(v.w - __bfloat162float(h23.y));
    uint2 uh = make_uint2(*(uint32_t*)&h01, *(uint32_t*)&h23);
    uint2 ul = make_uint2(*(uint32_t*)&l01, *(uint32_t*)&l23);
    *(uint2*)dh = uh;
    *(uint2*)dl = ul;
}

// ===========================================================================
// Kernel 1: QKV projection via mma.sync bf16 3-term split + RoPE epilogue.
// grid = (3 {q,k,v}, 64 m-tiles), block = 256 (8 warps, 4m x 2n).
// CTA tile: [128 m x 128 n], K-chunk = 64, double-buffered cp.async.
// ===========================================================================
#define ROWB 144                          // 64 bf16 = 128B + 16B pad
#define TILEB (128 * ROWB)                // 18432
#define BUFB (4 * TILEB)                  // Ahi, Alo, Bhi, Blo
#define GEMM_SMEM (2 * BUFB)              // 147456

__global__ __launch_bounds__(256) void proj_mma_kernel()
{
    extern __shared__ __align__(16) char smem[];
    const int tid = threadIdx.x;
    const int wid = tid >> 5;
    const int lane = tid & 31;
    const int warpM = wid & 3;            // 32 rows each
    const int warpN = wid >> 2;           // 64 cols each
    const int mz = blockIdx.x;
    const int mt = blockIdx.y;

    const uint32_t sb = smem_to_u32(smem);

    const __nv_bfloat16* __restrict__ ah_src = g_xh + (size_t)mt * 128 * D_MODEL;
    const __nv_bfloat16* __restrict__ al_src = g_xl + (size_t)mt * 128 * D_MODEL;
    const __nv_bfloat16* __restrict__ bh_src = g_wh + (size_t)mz * HEAD * D_MODEL;
    const __nv_bfloat16* __restrict__ bl_src = g_wl + (size_t)mz * HEAD * D_MODEL;

    const int cc = tid & 7;               // 16B chunk within row
    const int r0 = tid >> 3;              // 0..31

    // ldmatrix per-lane offsets (bytes)
    const uint32_t laneA = (uint32_t)((lane & 15) * ROWB + ((lane & 16) ? 16 : 0));
    const uint32_t laneB = (uint32_t)(((lane & 7) + ((lane & 16) ? 8 : 0)) * ROWB
                                      + ((lane & 8) ? 16 : 0));

    float acc[2][8][4];
#pragma unroll
    for (int mf = 0; mf < 2; mf++)
#pragma unroll
        for (int nf = 0; nf < 8; nf++)
#pragma unroll
            for (int e = 0; e < 4; e++) acc[mf][nf][e] = 0.f;

    // ---- async load of one k-chunk into buffer ----
    auto load_chunk = [&](int c, int buf) {
        const int k0 = c * 64;
        uint32_t d0 = sb + buf * BUFB;
#pragma unroll
        for (int i = 0; i < 4; i++) {
            int r = r0 + i * 32;
            size_t goff = (size_t)r * D_MODEL + k0 + cc * 8;
            uint32_t soff = (uint32_t)(r * ROWB + cc * 16);
            CP_ASYNC16(d0 + 0 * TILEB + soff, ah_src + goff);
            CP_ASYNC16(d0 + 1 * TILEB + soff, al_src + goff);
            CP_ASYNC16(d0 + 2 * TILEB + soff, bh_src + goff);
            CP_ASYNC16(d0 + 3 * TILEB + soff, bl_src + goff);
        }
    };

    load_chunk(0, 0);
    CP_COMMIT;

    for (int c = 0; c < 64; c++) {
        const int buf = c & 1;
        if (c < 63) {
            load_chunk(c + 1, buf ^ 1);
            CP_COMMIT;
            CP_WAIT(1);
        } else {
            CP_WAIT(0);
        }
        __syncthreads();

        const uint32_t bbase = sb + buf * BUFB;
        const uint32_t aHi = bbase;
        const uint32_t aLo = bbase + TILEB;
        const uint32_t bHi = bbase + 2 * TILEB;
        const uint32_t bLo = bbase + 3 * TILEB;

#pragma unroll 1
        for (int ks = 0; ks < 4; ks++) {
            const uint32_t ko = (uint32_t)(ks * 32);   // 16 bf16 = 32B
            uint32_t ahf[2][4], alf[2][4];
#pragma unroll
            for (int mf = 0; mf < 2; mf++) {
                uint32_t mo = (uint32_t)((warpM * 32 + mf * 16) * ROWB) + ko + laneA;
                ldm_x4(ahf[mf], aHi + mo);
                ldm_x4(alf[mf], aLo + mo);
            }
            uint32_t bhf[4][4], blf[4][4];
#pragma unroll
            for (int j = 0; j < 4; j++) {
                uint32_t no = (uint32_t)((warpN * 64 + j * 16) * ROWB) + ko + laneB;
                ldm_x4(bhf[j], bHi + no);
                ldm_x4(blf[j], bLo + no);
            }
#pragma unroll
            for (int mf = 0; mf < 2; mf++)
#pragma unroll
                for (int nf = 0; nf < 8; nf++) {
                    uint32_t b0 = bhf[nf >> 1][(nf & 1) * 2];
                    uint32_t b1 = bhf[nf >> 1][(nf & 1) * 2 + 1];
                    mma16816(acc[mf][nf], ahf[mf], b0, b1);       // hh
                    uint32_t c0 = blf[nf >> 1][(nf & 1) * 2];
                    uint32_t c1 = blf[nf >> 1][(nf & 1) * 2 + 1];
                    mma16816(acc[mf][nf], ahf[mf], c0, c1);       // hl
                    mma16816(acc[mf][nf], alf[mf], b0, b1);       // lh
                }
        }
        __syncthreads();
    }

    // ---- epilogue: RoPE (q,k) + store fp32 ----
    float* __restrict__ dst = (mz == 0) ? g_q : (mz == 1) ? g_k : g_v;
    const int qr = lane >> 2;
    const int qc = 2 * (lane & 3);

    float theta_nf[8];
#pragma unroll
    for (int nf = 0; nf < 8; nf++) {
        int p = warpN * 32 + nf * 4 + (lane & 3);
        theta_nf[nf] = (float)exp(-0.28782313662425574 * (double)p); // ln(1e4)/32
    }

#pragma unroll
    for (int mf = 0; mf < 2; mf++) {
#pragma unroll
        for (int nf = 0; nf < 8; nf++) {
            int row = warpM * 32 + mf * 16 + qr;
            int col = warpN * 64 + nf * 8 + qc;
            size_t mg0 = (size_t)mt * 128 + row;
            size_t mg1 = mg0 + 8;
            float x0 = acc[mf][nf][0], x1 = acc[mf][nf][1];
            float y0 = acc[mf][nf][2], y1 = acc[mf][nf][3];
            if (mz < 2) {
                float th = theta_nf[nf];
                float sn, cs;
                sincosf((float)(int)(mg0 & (SEQ - 1)) * th, &sn, &cs);
                float t0 = x0 * cs - x1 * sn;
                x1 = x1 * cs + x0 * sn; x0 = t0;
                sincosf((float)(int)(mg1 & (SEQ - 1)) * th, &sn, &cs);
                float t1 = y0 * cs - y1 * sn;
                y1 = y1 * cs + y0 * sn; y0 = t1;
            }
            *(float2*)&dst[mg0 * HEAD + col] = make_float2(x0, x1);
            *(float2*)&dst[mg1 * HEAD + col] = make_float2(y0, y1);
        }
    }
}

// ===========================================================================
// Kernel 2: causal flash attention, fp32, 512 threads / CTA.
// Threads [0,256) handle q-tile bx; [256,512) handle q-tile 127-bx,
// each in its own smem region, synced by named barriers.
// ===========================================================================
#define QST_OFF 0            // [128][34]
#define KST_OFF 4352         // [128][64] (xor-16 swizzled float4 groups)
#define VS_OFF  12544        // [64][132]
#define PST_OFF 20992        // [64][34]
#define ATTN_SMEM_FLOATS 23168
#define ATTN_SMEM_BYTES (2 * ATTN_SMEM_FLOATS * 4)

__device__ __forceinline__ void half_bar(int half) {
    asm volatile("bar.sync %0, 256;" :: "r"(half + 1) : "memory");
}

__global__ __launch_bounds__(512) void attn_kernel(float* __restrict__ out)
{
    extern __shared__ __align__(16) float sm[];
    const int half = threadIdx.x >> 8;
    const int tid = threadIdx.x & 255;
    float* base = sm + half * ATTN_SMEM_FLOATS;
    float* QsT = base + QST_OFF;
    float* KsT = base + KST_OFF;
    float* Vs  = base + VS_OFF;
    float* PsT = base + PST_OFF;

    const int ty = tid >> 4;
    const int tx = tid & 15;
    const int b = blockIdx.y;
    const float scale = 0.08838834764831845f;  // 1/sqrt(128)

    const int qt = half ? (127 - (int)blockIdx.x) : (int)blockIdx.x;
    const int qbase = qt * 32;

    const float* __restrict__ qsrc = g_q + ((size_t)b * SEQ + qbase) * HEAD;
#pragma unroll
    for (int i = 0; i < 4; i++) {
        int fidx = i * 256 + tid;
        int r = fidx >> 5, c4 = fidx & 31;
        float4 v = *(const float4*)(qsrc + (size_t)r * HEAD + c4 * 4);
        QsT[(c4 * 4 + 0) * 34 + r] = v.x * scale;
        QsT[(c4 * 4 + 1) * 34 + r] = v.y * scale;
        QsT[(c4 * 4 + 2) * 34 + r] = v.z * scale;
        QsT[(c4 * 4 + 3) * 34 + r] = v.w * scale;
    }

    float m_run[2] = {-INFINITY, -INFINITY};
    float l_run[2] = {0.f, 0.f};
    float o[2][8];
#pragma unroll
    for (int i = 0; i < 2; i++)
#pragma unroll
        for (int j = 0; j < 8; j++) o[i][j] = 0.f;

    const int ntiles = (qbase + 32 + 63) >> 6;
    for (int kt = 0; kt < ntiles; kt++) {
        const int kbase = kt * 64;
        half_bar(half);
        const float* __restrict__ ksrc = g_k + ((size_t)b * SEQ + kbase) * HEAD;
        const float* __restrict__ vsrc = g_v + ((size_t)b * SEQ + kbase) * HEAD;
#pragma unroll
        for (int i = 0; i < 8; i++) {
            int fidx = i * 256 + tid;
            int r = fidx >> 5, c4 = fidx & 31;
            float4 kv = *(const float4*)(ksrc + (size_t)r * HEAD + c4 * 4);
            int k0 = c4 * 4;
            KsT[(k0 + 0) * 64 + ((((r >> 2) ^ ((k0 + 0) & 15))) << 2) + (r & 3)] = kv.x;
            KsT[(k0 + 1) * 64 + ((((r >> 2) ^ ((k0 + 1) & 15))) << 2) + (r & 3)] = kv.y;
            KsT[(k0 + 2) * 64 + ((((r >> 2) ^ ((k0 + 2) & 15))) << 2) + (r & 3)] = kv.z;
            KsT[(k0 + 3) * 64 + ((((r >> 2) ^ ((k0 + 3) & 15))) << 2) + (r & 3)] = kv.w;
            float4 vv = *(const float4*)(vsrc + (size_t)r * HEAD + c4 * 4);
            *(float4*)&Vs[r * 132 + c4 * 4] = vv;
        }
        half_bar(half);

        float sacc[2][4];
#pragma unroll
        for (int i = 0; i < 2; i++)
#pragma unroll
            for (int j = 0; j < 4; j++) sacc[i][j] = 0.f;

#pragma unroll 8
        for (int k = 0; k < 128; k++) {
            float2 a = *(const float2*)(QsT + k * 34 + ty * 2);
            float4 bq = *(const float4*)(KsT + k * 64 + ((tx ^ (k & 15)) << 2));
            sacc[0][0] += a.x * bq.x; sacc[0][1] += a.x * bq.y;
            sacc[0][2] += a.x * bq.z; sacc[0][3] += a.x * bq.w;
            sacc[1][0] += a.y * bq.x; sacc[1][1] += a.y * bq.y;
            sacc[1][2] += a.y * bq.z; sacc[1][3] += a.y * bq.w;
        }

#pragma unroll
        for (int i = 0; i < 2; i++) {
            int qrow = qbase + ty * 2 + i;
#pragma unroll
            for (int j = 0; j < 4; j++)
                if (kbase + tx * 4 + j > qrow) sacc[i][j] = -INFINITY;
        }

#pragma unroll
        for (int i = 0; i < 2; i++) {
            float mx = fmaxf(fmaxf(sacc[i][0], sacc[i][1]),
                             fmaxf(sacc[i][2], sacc[i][3]));
#pragma unroll
            for (int off = 8; off >= 1; off >>= 1)
                mx = fmaxf(mx, __shfl_xor_sync(0xffffffffu, mx, off));
            float mn = fmaxf(m_run[i], mx);
            float alpha = expf(m_run[i] - mn);
            float p0 = expf(sacc[i][0] - mn);
            float p1 = expf(sacc[i][1] - mn);
            float p2 = expf(sacc[i][2] - mn);
            float p3 = expf(sacc[i][3] - mn);
            float rs = (p0 + p1) + (p2 + p3);
#pragma unroll
            for (int off = 8; off >= 1; off >>= 1)
                rs += __shfl_xor_sync(0xffffffffu, rs, off);
            l_run[i] = l_run[i] * alpha + rs;
            m_run[i] = mn;
#pragma unroll
            for (int j = 0; j < 8; j++) o[i][j] *= alpha;
            PsT[(tx * 4 + 0) * 34 + ty * 2 + i] = p0;
            PsT[(tx * 4 + 1) * 34 + ty * 2 + i] = p1;
            PsT[(tx * 4 + 2) * 34 + ty * 2 + i] = p2;
            PsT[(tx * 4 + 3) * 34 + ty * 2 + i] = p3;
        }
        half_bar(half);

#pragma unroll 8
        for (int j = 0; j < 64; j++) {
            float2 a = *(const float2*)(PsT + j * 34 + ty * 2);
            float4 b0 = *(const float4*)(Vs + j * 132 + tx * 8);
            float4 b1 = *(const float4*)(Vs + j * 132 + tx * 8 + 4);
            o[0][0] += a.x * b0.x; o[0][1] += a.x * b0.y;
            o[0][2] += a.x * b0.z; o[0][3] += a.x * b0.w;
            o[0][4] += a.x * b1.x; o[0][5] += a.x * b1.y;
            o[0][6] += a.x * b1.z; o[0][7] += a.x * b1.w;
            o[1][0] += a.y * b0.x; o[1][1] += a.y * b0.y;
            o[1][2] += a.y * b0.z; o[1][3] += a.y * b0.w;
            o[1][4] += a.y * b1.x; o[1][5] += a.y * b1.y;
            o[1][6] += a.y * b1.z; o[1][7] += a.y * b1.w;
        }
    }

    float* __restrict__ orow = out + ((size_t)b * SEQ + qbase) * HEAD;
#pragma unroll
    for (int i = 0; i < 2; i++) {
        float inv = 1.f / l_run[i];
        float4 r0 = make_float4(o[i][0] * inv, o[i][1] * inv,
                                o[i][2] * inv, o[i][3] * inv);
        float4 r1 = make_float4(o[i][4] * inv, o[i][5] * inv,
                                o[i][6] * inv, o[i][7] * inv);
        *(float4*)&orow[(size_t)(ty * 2 + i) * HEAD + tx * 8]     = r0;
        *(float4*)&orow[(size_t)(ty * 2 + i) * HEAD + tx * 8 + 4] = r1;
    }
}

extern "C" void kernel_launch(void* const* d_in, const int* in_sizes, int n_in,
                              void* d_out, int out_size)
{
    const float* x  = (const float*)d_in[0];
    const float* Wq = (const float*)d_in[1];
    const float* Wk = (const float*)d_in[2];
    const float* Wv = (const float*)d_in[3];
    float* out = (float*)d_out;

    cudaFuncSetAttribute((const void*)proj_mma_kernel,
                         cudaFuncAttributeMaxDynamicSharedMemorySize, GEMM_SMEM);
    cudaFuncSetAttribute((const void*)attn_kernel,
                         cudaFuncAttributeMaxDynamicSharedMemorySize, ATTN_SMEM_BYTES);

    conv_kernel<<<CONV_BLOCKS, 256>>>(x, Wq, Wk, Wv);
    proj_mma_kernel<<<dim3(3, 64), 256, GEMM_SMEM>>>();
    attn_kernel<<<dim3(64, BATCH), 512, ATTN_SMEM_BYTES>>>(out);
}

// round 9
// speedup vs baseline: 3.0094x; 1.7344x over previous
#include <cuda_runtime.h>
#include <cuda_bf16.h>
#include <math.h>
#include <stdint.h>

#define D_MODEL 4096
#define HEAD 128
#define SEQ 4096
#define BATCH 2

// bf16 hi/lo split operands (allocation-free rule: static __device__ arrays)
__device__ __align__(16) __nv_bfloat16 g_xh[BATCH * SEQ * D_MODEL];
__device__ __align__(16) __nv_bfloat16 g_xl[BATCH * SEQ * D_MODEL];
__device__ __align__(16) __nv_bfloat16 g_wh[3 * HEAD * D_MODEL];
__device__ __align__(16) __nv_bfloat16 g_wl[3 * HEAD * D_MODEL];

// q/k/v as bf16 hi/lo (q pre-scaled by 1/sqrt(128))
__device__ __align__(16) __nv_bfloat16 g_qh[BATCH * SEQ * HEAD];
__device__ __align__(16) __nv_bfloat16 g_ql[BATCH * SEQ * HEAD];
__device__ __align__(16) __nv_bfloat16 g_kh[BATCH * SEQ * HEAD];
__device__ __align__(16) __nv_bfloat16 g_kl[BATCH * SEQ * HEAD];
__device__ __align__(16) __nv_bfloat16 g_vh[BATCH * SEQ * HEAD];
__device__ __align__(16) __nv_bfloat16 g_vl[BATCH * SEQ * HEAD];

__device__ __forceinline__ uint32_t smem_to_u32(const void* smem_ptr) {
    uint32_t addr;
    asm("{ .reg .u64 tmp; cvta.to.shared.u64 tmp, %1; cvt.u32.u64 %0, tmp; }"
        : "=r"(addr) : "l"(smem_ptr));
    return addr;
}

#define CP_ASYNC16(dst, src) \
    asm volatile("cp.async.cg.shared.global [%0], [%1], 16;" \
                 :: "r"(dst), "l"(src) : "memory")
#define CP_COMMIT asm volatile("cp.async.commit_group;" ::: "memory")
#define CP_WAIT(n) asm volatile("cp.async.wait_group %0;" :: "n"(n) : "memory")

__device__ __forceinline__ void ldm_x4(uint32_t* r, uint32_t addr) {
    asm volatile("ldmatrix.sync.aligned.m8n8.x4.shared.b16 {%0,%1,%2,%3}, [%4];"
                 : "=r"(r[0]), "=r"(r[1]), "=r"(r[2]), "=r"(r[3]) : "r"(addr));
}
__device__ __forceinline__ void ldm_x4_t(uint32_t* r, uint32_t addr) {
    asm volatile("ldmatrix.sync.aligned.m8n8.x4.trans.shared.b16 {%0,%1,%2,%3}, [%4];"
                 : "=r"(r[0]), "=r"(r[1]), "=r"(r[2]), "=r"(r[3]) : "r"(addr));
}

__device__ __forceinline__ void mma16816(float* c, const uint32_t* a,
                                         uint32_t b0, uint32_t b1) {
    asm volatile(
        "mma.sync.aligned.m16n8k16.row.col.f32.bf16.bf16.f32 "
        "{%0,%1,%2,%3}, {%4,%5,%6,%7}, {%8,%9}, {%0,%1,%2,%3};"
        : "+f"(c[0]), "+f"(c[1]), "+f"(c[2]), "+f"(c[3])
        : "r"(a[0]), "r"(a[1]), "r"(a[2]), "r"(a[3]), "r"(b0), "r"(b1));
}

// split two floats into bf16x2 hi and lo packed words
__device__ __forceinline__ void split2(float a, float b, uint32_t& h, uint32_t& l) {
    __nv_bfloat162 hh, ll;
    hh.x = __float2bfloat16_rn(a);
    hh.y = __float2bfloat16_rn(b);
    ll.x = __float2bfloat16_rn(a - __bfloat162float(hh.x));
    ll.y = __float2bfloat16_rn(b - __bfloat162float(hh.y));
    h = *(uint32_t*)&hh;
    l = *(uint32_t*)&ll;
}

// ===========================================================================
// Kernel 0: fp32 -> bf16 hi/lo split conversion for x and Wq/Wk/Wv.
// ===========================================================================
#define N4X (BATCH * SEQ * D_MODEL / 4)
#define N4W_PER (HEAD * D_MODEL / 4)
#define N4TOT (N4X + 3 * N4W_PER)
#define CONV_BLOCKS (N4TOT / 256)

__global__ __launch_bounds__(256) void conv_kernel(
    const float* __restrict__ x, const float* __restrict__ Wq,
    const float* __restrict__ Wk, const float* __restrict__ Wv)
{
    size_t i = (size_t)blockIdx.x * 256 + threadIdx.x;
    float4 v;
    __nv_bfloat16 *dh, *dl;
    if (i < N4X) {
        v = ((const float4*)x)[i];
        dh = g_xh + i * 4;
        dl = g_xl + i * 4;
    } else {
        size_t j = i - N4X;
        int mz = (int)(j / N4W_PER);
        size_t wj = j - (size_t)mz * N4W_PER;
        const float* W = (mz == 0) ? Wq : (mz == 1) ? Wk : Wv;
        v = ((const float4*)W)[wj];
        dh = g_wh + ((size_t)mz * N4W_PER + wj) * 4;
        dl = g_wl + ((size_t)mz * N4W_PER + wj) * 4;
    }
    uint32_t h01, h23, l01, l23;
    split2(v.x, v.y, h01, l01);
    split2(v.z, v.w, h23, l23);
    *(uint2*)dh = make_uint2(h01, h23);
    *(uint2*)dl = make_uint2(l01, l23);
}

// ===========================================================================
// Kernel 1: QKV projection via mma.sync bf16 3-term split + RoPE epilogue.
// grid = (3 {q,k,v}, 64 m-tiles), block = 256 (8 warps, 4m x 2n).
// Epilogue writes q/k/v as bf16 hi/lo (q pre-scaled).
// ===========================================================================
#define ROWB 144                          // 64 bf16 = 128B + 16B pad
#define TILEB (128 * ROWB)
#define BUFB (4 * TILEB)
#define GEMM_SMEM (2 * BUFB)              // 147456

__global__ __launch_bounds__(256) void proj_mma_kernel()
{
    extern __shared__ __align__(16) char smem[];
    const int tid = threadIdx.x;
    const int wid = tid >> 5;
    const int lane = tid & 31;
    const int warpM = wid & 3;
    const int warpN = wid >> 2;
    const int mz = blockIdx.x;
    const int mt = blockIdx.y;

    const uint32_t sb = smem_to_u32(smem);

    const __nv_bfloat16* __restrict__ ah_src = g_xh + (size_t)mt * 128 * D_MODEL;
    const __nv_bfloat16* __restrict__ al_src = g_xl + (size_t)mt * 128 * D_MODEL;
    const __nv_bfloat16* __restrict__ bh_src = g_wh + (size_t)mz * HEAD * D_MODEL;
    const __nv_bfloat16* __restrict__ bl_src = g_wl + (size_t)mz * HEAD * D_MODEL;

    const int cc = tid & 7;
    const int r0 = tid >> 3;

    const uint32_t laneA = (uint32_t)((lane & 15) * ROWB + ((lane & 16) ? 16 : 0));
    const uint32_t laneB = (uint32_t)(((lane & 7) + ((lane & 16) ? 8 : 0)) * ROWB
                                      + ((lane & 8) ? 16 : 0));

    float acc[2][8][4];
#pragma unroll
    for (int mf = 0; mf < 2; mf++)
#pragma unroll
        for (int nf = 0; nf < 8; nf++)
#pragma unroll
            for (int e = 0; e < 4; e++) acc[mf][nf][e] = 0.f;

    auto load_chunk = [&](int c, int buf) {
        const int k0 = c * 64;
        uint32_t d0 = sb + buf * BUFB;
#pragma unroll
        for (int i = 0; i < 4; i++) {
            int r = r0 + i * 32;
            size_t goff = (size_t)r * D_MODEL + k0 + cc * 8;
            uint32_t soff = (uint32_t)(r * ROWB + cc * 16);
            CP_ASYNC16(d0 + 0 * TILEB + soff, ah_src + goff);
            CP_ASYNC16(d0 + 1 * TILEB + soff, al_src + goff);
            CP_ASYNC16(d0 + 2 * TILEB + soff, bh_src + goff);
            CP_ASYNC16(d0 + 3 * TILEB + soff, bl_src + goff);
        }
    };

    load_chunk(0, 0);
    CP_COMMIT;

    for (int c = 0; c < 64; c++) {
        const int buf = c & 1;
        if (c < 63) {
            load_chunk(c + 1, buf ^ 1);
            CP_COMMIT;
            CP_WAIT(1);
        } else {
            CP_WAIT(0);
        }
        __syncthreads();

        const uint32_t bbase = sb + buf * BUFB;
        const uint32_t aHi = bbase;
        const uint32_t aLo = bbase + TILEB;
        const uint32_t bHi = bbase + 2 * TILEB;
        const uint32_t bLo = bbase + 3 * TILEB;

#pragma unroll 1
        for (int ks = 0; ks < 4; ks++) {
            const uint32_t ko = (uint32_t)(ks * 32);
            uint32_t ahf[2][4], alf[2][4];
#pragma unroll
            for (int mf = 0; mf < 2; mf++) {
                uint32_t mo = (uint32_t)((warpM * 32 + mf * 16) * ROWB) + ko + laneA;
                ldm_x4(ahf[mf], aHi + mo);
                ldm_x4(alf[mf], aLo + mo);
            }
            uint32_t bhf[4][4], blf[4][4];
#pragma unroll
            for (int j = 0; j < 4; j++) {
                uint32_t no = (uint32_t)((warpN * 64 + j * 16) * ROWB) + ko + laneB;
                ldm_x4(bhf[j], bHi + no);
                ldm_x4(blf[j], bLo + no);
            }
#pragma unroll
            for (int mf = 0; mf < 2; mf++)
#pragma unroll
                for (int nf = 0; nf < 8; nf++) {
                    uint32_t b0 = bhf[nf >> 1][(nf & 1) * 2];
                    uint32_t b1 = bhf[nf >> 1][(nf & 1) * 2 + 1];
                    mma16816(acc[mf][nf], ahf[mf], b0, b1);       // hh
                    uint32_t c0 = blf[nf >> 1][(nf & 1) * 2];
                    uint32_t c1 = blf[nf >> 1][(nf & 1) * 2 + 1];
                    mma16816(acc[mf][nf], ahf[mf], c0, c1);       // hl
                    mma16816(acc[mf][nf], alf[mf], b0, b1);       // lh
                }
        }
        __syncthreads();
    }

    // ---- epilogue: RoPE (q,k) + q scale + bf16 hi/lo store ----
    __nv_bfloat16 *dh, *dl;
    if (mz == 0)      { dh = g_qh; dl = g_ql; }
    else if (mz == 1) { dh = g_kh; dl = g_kl; }
    else              { dh = g_vh; dl = g_vl; }

    const int qr = lane >> 2;
    const int qc = 2 * (lane & 3);
    const float qscale = 0.08838834764831845f;  // 1/sqrt(128)

    float theta_nf[8];
#pragma unroll
    for (int nf = 0; nf < 8; nf++) {
        int p = warpN * 32 + nf * 4 + (lane & 3);
        theta_nf[nf] = (float)exp(-0.28782313662425574 * (double)p); // ln(1e4)/32
    }

#pragma unroll
    for (int mf = 0; mf < 2; mf++) {
#pragma unroll
        for (int nf = 0; nf < 8; nf++) {
            int row = warpM * 32 + mf * 16 + qr;
            int col = warpN * 64 + nf * 8 + qc;
            size_t mg0 = (size_t)mt * 128 + row;
            size_t mg1 = mg0 + 8;
            float x0 = acc[mf][nf][0], x1 = acc[mf][nf][1];
            float y0 = acc[mf][nf][2], y1 = acc[mf][nf][3];
            if (mz < 2) {
                float th = theta_nf[nf];
                float sn, cs;
                sincosf((float)(int)(mg0 & (SEQ - 1)) * th, &sn, &cs);
                float t0 = x0 * cs - x1 * sn;
                x1 = x1 * cs + x0 * sn; x0 = t0;
                sincosf((float)(int)(mg1 & (SEQ - 1)) * th, &sn, &cs);
                float t1 = y0 * cs - y1 * sn;
                y1 = y1 * cs + y0 * sn; y0 = t1;
            }
            if (mz == 0) { x0 *= qscale; x1 *= qscale; y0 *= qscale; y1 *= qscale; }
            uint32_t h, l;
            split2(x0, x1, h, l);
            *(uint32_t*)&dh[mg0 * HEAD + col] = h;
            *(uint32_t*)&dl[mg0 * HEAD + col] = l;
            split2(y0, y1, h, l);
            *(uint32_t*)&dh[mg1 * HEAD + col] = h;
            *(uint32_t*)&dl[mg1 * HEAD + col] = l;
        }
    }
}

// ===========================================================================
// Kernel 2: causal flash attention via mma.sync bf16 (3-term split QK and PV).
// grid = (64 q-tiles, BATCH), block = 128 (4 warps, warp = 16 q rows).
// k-tile = 64 keys, double-buffered cp.async stages of {Kh,Kl,Vh,Vl}.
// ===========================================================================
#define RB 272                          // 128 bf16 = 256B + 16B pad
#define ARRB (64 * RB)                  // 17408
#define STAGEB (4 * ARRB)               // 69632
#define QH_OFF 0
#define QL_OFF ARRB
#define ST_OFF (2 * ARRB)
#define ATTN_SMEM (ST_OFF + 2 * STAGEB) // 174080

__global__ __launch_bounds__(128, 1) void attn_kernel(float* __restrict__ out)
{
    extern __shared__ __align__(16) char smem[];
    const uint32_t sb = smem_to_u32(smem);
    const int tid = threadIdx.x;
    const int wid = tid >> 5;
    const int lane = tid & 31;
    const int qt = blockIdx.x;
    const int b = blockIdx.y;
    const int qbase = qt * 64;

    const uint32_t laneA = (uint32_t)((lane & 15) * RB + ((lane & 16) ? 16 : 0));
    const uint32_t laneB = (uint32_t)(((lane & 7) + ((lane & 16) ? 8 : 0)) * RB
                                      + ((lane & 8) ? 16 : 0));

    // ---- issue Q loads (group 0) ----
    {
        const __nv_bfloat16* qh = g_qh + ((size_t)b * SEQ + qbase) * HEAD;
        const __nv_bfloat16* ql = g_ql + ((size_t)b * SEQ + qbase) * HEAD;
#pragma unroll
        for (int i = 0; i < 8; i++) {
            int idx = i * 128 + tid;
            int row = idx >> 4, c = idx & 15;
            uint32_t doff = (uint32_t)(row * RB + c * 16);
            size_t goff = (size_t)row * HEAD + c * 8;
            CP_ASYNC16(sb + QH_OFF + doff, qh + goff);
            CP_ASYNC16(sb + QL_OFF + doff, ql + goff);
        }
        CP_COMMIT;
    }

    auto issue = [&](int kt2, int st2) {
        const size_t gof = ((size_t)b * SEQ + kt2 * 64) * HEAD;
        const __nv_bfloat16* s0 = g_kh + gof;
        const __nv_bfloat16* s1 = g_kl + gof;
        const __nv_bfloat16* s2 = g_vh + gof;
        const __nv_bfloat16* s3 = g_vl + gof;
        const uint32_t d = sb + ST_OFF + st2 * STAGEB;
#pragma unroll
        for (int i = 0; i < 8; i++) {
            int idx = i * 128 + tid;
            int row = idx >> 4, c = idx & 15;
            uint32_t doff = (uint32_t)(row * RB + c * 16);
            size_t goff = (size_t)row * HEAD + c * 8;
            CP_ASYNC16(d + 0 * ARRB + doff, s0 + goff);
            CP_ASYNC16(d + 1 * ARRB + doff, s1 + goff);
            CP_ASYNC16(d + 2 * ARRB + doff, s2 + goff);
            CP_ASYNC16(d + 3 * ARRB + doff, s3 + goff);
        }
    };

    issue(0, 0);
    CP_COMMIT;
    CP_WAIT(1);       // Q done (KV tile 0 may still be in flight)
    __syncthreads();

    // ---- extract persistent Q fragments ----
    uint32_t Qhf[8][4], Qlf[8][4];
#pragma unroll
    for (int ks = 0; ks < 8; ks++) {
        uint32_t mo = (uint32_t)((16 * wid) * RB + ks * 32) + laneA;
        ldm_x4(Qhf[ks], sb + QH_OFF + mo);
        ldm_x4(Qlf[ks], sb + QL_OFF + mo);
    }

    float o[16][4];
#pragma unroll
    for (int j = 0; j < 16; j++)
#pragma unroll
        for (int e = 0; e < 4; e++) o[j][e] = 0.f;
    float mA = -1e30f, mB = -1e30f, lA = 0.f, lB = 0.f;

    const int rA = qbase + 16 * wid + (lane >> 2);

    for (int kt = 0; kt <= qt; kt++) {
        const int st = kt & 1;
        if (kt < qt) {
            issue(kt + 1, st ^ 1);
            CP_COMMIT;
            CP_WAIT(1);
        } else {
            CP_WAIT(0);
        }
        __syncthreads();

        const uint32_t kh = sb + ST_OFF + st * STAGEB;
        const uint32_t kl = kh + ARRB;
        const uint32_t vh = kh + 2 * ARRB;
        const uint32_t vl = kh + 3 * ARRB;

        // ---- S = Q K^T (3 terms) ----
        float sacc[8][4];
#pragma unroll
        for (int j = 0; j < 8; j++)
#pragma unroll
            for (int e = 0; e < 4; e++) sacc[j][e] = 0.f;

#pragma unroll 1
        for (int g = 0; g < 4; g++) {
            const uint32_t gb = (uint32_t)((16 * g) * RB) + laneB;
#pragma unroll
            for (int ks = 0; ks < 8; ks++) {
                uint32_t kf[4], lf[4];
                ldm_x4(kf, kh + gb + ks * 32);
                ldm_x4(lf, kl + gb + ks * 32);
                mma16816(sacc[2 * g],     Qhf[ks], kf[0], kf[1]);
                mma16816(sacc[2 * g + 1], Qhf[ks], kf[2], kf[3]);
                mma16816(sacc[2 * g],     Qlf[ks], kf[0], kf[1]);
                mma16816(sacc[2 * g + 1], Qlf[ks], kf[2], kf[3]);
                mma16816(sacc[2 * g],     Qhf[ks], lf[0], lf[1]);
                mma16816(sacc[2 * g + 1], Qhf[ks], lf[2], lf[3]);
            }
        }

        // ---- causal mask (diagonal tile only) ----
        if (kt == qt) {
            const int cb = qbase + 2 * (lane & 3);
#pragma unroll
            for (int j = 0; j < 8; j++) {
                int col = cb + 8 * j;
                if (col > rA)     sacc[j][0] = -1e30f;
                if (col + 1 > rA) sacc[j][1] = -1e30f;
                if (col > rA + 8)     sacc[j][2] = -1e30f;
                if (col + 1 > rA + 8) sacc[j][3] = -1e30f;
            }
        }

        // ---- online softmax ----
        float mxA = -1e30f, mxB = -1e30f;
#pragma unroll
        for (int j = 0; j < 8; j++) {
            mxA = fmaxf(mxA, fmaxf(sacc[j][0], sacc[j][1]));
            mxB = fmaxf(mxB, fmaxf(sacc[j][2], sacc[j][3]));
        }
        mxA = fmaxf(mxA, __shfl_xor_sync(0xffffffffu, mxA, 1));
        mxA = fmaxf(mxA, __shfl_xor_sync(0xffffffffu, mxA, 2));
        mxB = fmaxf(mxB, __shfl_xor_sync(0xffffffffu, mxB, 1));
        mxB = fmaxf(mxB, __shfl_xor_sync(0xffffffffu, mxB, 2));

        float mAn = fmaxf(mA, mxA), mBn = fmaxf(mB, mxB);
        float alphaA = __expf(mA - mAn), alphaB = __expf(mB - mBn);
        float sA = 0.f, sB = 0.f;
#pragma unroll
        for (int j = 0; j < 8; j++) {
            sacc[j][0] = __expf(sacc[j][0] - mAn);
            sacc[j][1] = __expf(sacc[j][1] - mAn);
            sacc[j][2] = __expf(sacc[j][2] - mBn);
            sacc[j][3] = __expf(sacc[j][3] - mBn);
            sA += sacc[j][0] + sacc[j][1];
            sB += sacc[j][2] + sacc[j][3];
        }
        sA += __shfl_xor_sync(0xffffffffu, sA, 1);
        sA += __shfl_xor_sync(0xffffffffu, sA, 2);
        sB += __shfl_xor_sync(0xffffffffu, sB, 1);
        sB += __shfl_xor_sync(0xffffffffu, sB, 2);
        lA = lA * alphaA + sA;
        lB = lB * alphaB + sB;
        mA = mAn; mB = mBn;
#pragma unroll
        for (int j = 0; j < 16; j++) {
            o[j][0] *= alphaA; o[j][1] *= alphaA;
            o[j][2] *= alphaB; o[j][3] *= alphaB;
        }

        // ---- O += P V (3 terms; P split exactly into hi/lo) ----
#pragma unroll 1
        for (int t = 0; t < 4; t++) {
            uint32_t aH[4], aL[4];
            split2(sacc[2 * t][0],     sacc[2 * t][1],     aH[0], aL[0]);
            split2(sacc[2 * t][2],     sacc[2 * t][3],     aH[1], aL[1]);
            split2(sacc[2 * t + 1][0], sacc[2 * t + 1][1], aH[2], aL[2]);
            split2(sacc[2 * t + 1][2], sacc[2 * t + 1][3], aH[3], aL[3]);
            const uint32_t tb = (uint32_t)((16 * t) * RB) + laneA;
#pragma unroll
            for (int ng = 0; ng < 8; ng++) {
                uint32_t vf[4], wf[4];
                ldm_x4_t(vf, vh + tb + ng * 32);
                ldm_x4_t(wf, vl + tb + ng * 32);
                mma16816(o[2 * ng],     aH, vf[0], vf[1]);
                mma16816(o[2 * ng + 1], aH, vf[2], vf[3]);
                mma16816(o[2 * ng],     aL, vf[0], vf[1]);
                mma16816(o[2 * ng + 1], aL, vf[2], vf[3]);
                mma16816(o[2 * ng],     aH, wf[0], wf[1]);
                mma16816(o[2 * ng + 1], aH, wf[2], wf[3]);
            }
        }
        __syncthreads();
    }

    // ---- write output ----
    const float iA = 1.f / lA, iB = 1.f / lB;
    float* orow0 = out + ((size_t)b * SEQ + rA) * HEAD;
    float* orow1 = out + ((size_t)b * SEQ + rA + 8) * HEAD;
#pragma unroll
    for (int j = 0; j < 16; j++) {
        int col = 8 * j + 2 * (lane & 3);
        *(float2*)&orow0[col] = make_float2(o[j][0] * iA, o[j][1] * iA);
        *(float2*)&orow1[col] = make_float2(o[j][2] * iB, o[j][3] * iB);
    }
}

extern "C" void kernel_launch(void* const* d_in, const int* in_sizes, int n_in,
                              void* d_out, int out_size)
{
    const float* x  = (const float*)d_in[0];
    const float* Wq = (const float*)d_in[1];
    const float* Wk = (const float*)d_in[2];
    const float* Wv = (const float*)d_in[3];
    float* out = (float*)d_out;

    cudaFuncSetAttribute((const void*)proj_mma_kernel,
                         cudaFuncAttributeMaxDynamicSharedMemorySize, GEMM_SMEM);
    cudaFuncSetAttribute((const void*)attn_kernel,
                         cudaFuncAttributeMaxDynamicSharedMemorySize, ATTN_SMEM);

    conv_kernel<<<CONV_BLOCKS, 256>>>(x, Wq, Wk, Wv);
    proj_mma_kernel<<<dim3(3, 64), 256, GEMM_SMEM>>>();
    attn_kernel<<<dim3(64, BATCH), 128, ATTN_SMEM>>>(out);
}

// round 16
// speedup vs baseline: 3.6609x; 1.2165x over previous
#include <cuda_runtime.h>
#include <cuda_bf16.h>
#include <math.h>
#include <stdint.h>

#define D_MODEL 4096
#define HEAD 128
#define SEQ 4096
#define BATCH 2

// bf16 hi/lo split operands (allocation-free rule: static __device__ arrays)
__device__ __align__(16) __nv_bfloat16 g_xh[BATCH * SEQ * D_MODEL];
__device__ __align__(16) __nv_bfloat16 g_xl[BATCH * SEQ * D_MODEL];
__device__ __align__(16) __nv_bfloat16 g_wh[3 * HEAD * D_MODEL];
__device__ __align__(16) __nv_bfloat16 g_wl[3 * HEAD * D_MODEL];

// q/k/v as bf16 hi/lo (q pre-scaled by 1/sqrt(128))
__device__ __align__(16) __nv_bfloat16 g_qh[BATCH * SEQ * HEAD];
__device__ __align__(16) __nv_bfloat16 g_ql[BATCH * SEQ * HEAD];
__device__ __align__(16) __nv_bfloat16 g_kh[BATCH * SEQ * HEAD];
__device__ __align__(16) __nv_bfloat16 g_kl[BATCH * SEQ * HEAD];
__device__ __align__(16) __nv_bfloat16 g_vh[BATCH * SEQ * HEAD];
__device__ __align__(16) __nv_bfloat16 g_vl[BATCH * SEQ * HEAD];

// split-K attention partials
#define IPB 144                       // items per batch (sum ceil((qt+1)/4), qt<32)
#define NITEMS (2 * IPB)              // 288
__device__ float g_po[NITEMS * 128 * 128];   // unnormalized partial O
__device__ float g_pm[NITEMS * 128];         // row max
__device__ float g_pl[NITEMS * 128];         // row sum

__device__ __forceinline__ uint32_t smem_to_u32(const void* smem_ptr) {
    uint32_t addr;
    asm("{ .reg .u64 tmp; cvta.to.shared.u64 tmp, %1; cvt.u32.u64 %0, tmp; }"
        : "=r"(addr) : "l"(smem_ptr));
    return addr;
}

#define CP_ASYNC16(dst, src) \
    asm volatile("cp.async.cg.shared.global [%0], [%1], 16;" \
                 :: "r"(dst), "l"(src) : "memory")
#define CP_COMMIT asm volatile("cp.async.commit_group;" ::: "memory")
#define CP_WAIT(n) asm volatile("cp.async.wait_group %0;" :: "n"(n) : "memory")

__device__ __forceinline__ void ldm_x4(uint32_t* r, uint32_t addr) {
    asm volatile("ldmatrix.sync.aligned.m8n8.x4.shared.b16 {%0,%1,%2,%3}, [%4];"
                 : "=r"(r[0]), "=r"(r[1]), "=r"(r[2]), "=r"(r[3]) : "r"(addr));
}
__device__ __forceinline__ void ldm_x4_t(uint32_t* r, uint32_t addr) {
    asm volatile("ldmatrix.sync.aligned.m8n8.x4.trans.shared.b16 {%0,%1,%2,%3}, [%4];"
                 : "=r"(r[0]), "=r"(r[1]), "=r"(r[2]), "=r"(r[3]) : "r"(addr));
}

__device__ __forceinline__ void mma16816(float* c, const uint32_t* a,
                                         uint32_t b0, uint32_t b1) {
    asm volatile(
        "mma.sync.aligned.m16n8k16.row.col.f32.bf16.bf16.f32 "
        "{%0,%1,%2,%3}, {%4,%5,%6,%7}, {%8,%9}, {%0,%1,%2,%3};"
        : "+f"(c[0]), "+f"(c[1]), "+f"(c[2]), "+f"(c[3])
        : "r"(a[0]), "r"(a[1]), "r"(a[2]), "r"(a[3]), "r"(b0), "r"(b1));
}

__device__ __forceinline__ void split2(float a, float b, uint32_t& h, uint32_t& l) {
    __nv_bfloat162 hh, ll;
    hh.x = __float2bfloat16_rn(a);
    hh.y = __float2bfloat16_rn(b);
    ll.x = __float2bfloat16_rn(a - __bfloat162float(hh.x));
    ll.y = __float2bfloat16_rn(b - __bfloat162float(hh.y));
    h = *(uint32_t*)&hh;
    l = *(uint32_t*)&ll;
}

// ===========================================================================
// Kernel 0: fp32 -> bf16 hi/lo split conversion for x and Wq/Wk/Wv.
// ===========================================================================
#define N4X (BATCH * SEQ * D_MODEL / 4)
#define N4W_PER (HEAD * D_MODEL / 4)
#define N4TOT (N4X + 3 * N4W_PER)
#define CONV_BLOCKS (N4TOT / 256)

__global__ __launch_bounds__(256) void conv_kernel(
    const float* __restrict__ x, const float* __restrict__ Wq,
    const float* __restrict__ Wk, const float* __restrict__ Wv)
{
    size_t i = (size_t)blockIdx.x * 256 + threadIdx.x;
    float4 v;
    __nv_bfloat16 *dh, *dl;
    if (i < N4X) {
        v = ((const float4*)x)[i];
        dh = g_xh + i * 4;
        dl = g_xl + i * 4;
    } else {
        size_t j = i - N4X;
        int mz = (int)(j / N4W_PER);
        size_t wj = j - (size_t)mz * N4W_PER;
        const float* W = (mz == 0) ? Wq : (mz == 1) ? Wk : Wv;
        v = ((const float4*)W)[wj];
        dh = g_wh + ((size_t)mz * N4W_PER + wj) * 4;
        dl = g_wl + ((size_t)mz * N4W_PER + wj) * 4;
    }
    uint32_t h01, h23, l01, l23;
    split2(v.x, v.y, h01, l01);
    split2(v.z, v.w, h23, l23);
    *(uint2*)dh = make_uint2(h01, h23);
    *(uint2*)dl = make_uint2(l01, l23);
}

// ===========================================================================
// Kernel 1: QKV projection via mma.sync bf16 3-term split + RoPE epilogue.
// grid = (3 {q,k,v}, 64 m-tiles), block = 256 (8 warps, 4m x 2n).
// ===========================================================================
#define ROWB 144
#define TILEB (128 * ROWB)
#define BUFB (4 * TILEB)
#define GEMM_SMEM (2 * BUFB)

__global__ __launch_bounds__(256) void proj_mma_kernel()
{
    extern __shared__ __align__(16) char smem[];
    const int tid = threadIdx.x;
    const int wid = tid >> 5;
    const int lane = tid & 31;
    const int warpM = wid & 3;
    const int warpN = wid >> 2;
    const int mz = blockIdx.x;
    const int mt = blockIdx.y;

    const uint32_t sb = smem_to_u32(smem);

    const __nv_bfloat16* __restrict__ ah_src = g_xh + (size_t)mt * 128 * D_MODEL;
    const __nv_bfloat16* __restrict__ al_src = g_xl + (size_t)mt * 128 * D_MODEL;
    const __nv_bfloat16* __restrict__ bh_src = g_wh + (size_t)mz * HEAD * D_MODEL;
    const __nv_bfloat16* __restrict__ bl_src = g_wl + (size_t)mz * HEAD * D_MODEL;

    const int cc = tid & 7;
    const int r0 = tid >> 3;

    const uint32_t laneA = (uint32_t)((lane & 15) * ROWB + ((lane & 16) ? 16 : 0));
    const uint32_t laneB = (uint32_t)(((lane & 7) + ((lane & 16) ? 8 : 0)) * ROWB
                                      + ((lane & 8) ? 16 : 0));

    float acc[2][8][4];
#pragma unroll
    for (int mf = 0; mf < 2; mf++)
#pragma unroll
        for (int nf = 0; nf < 8; nf++)
#pragma unroll
            for (int e = 0; e < 4; e++) acc[mf][nf][e] = 0.f;

    auto load_chunk = [&](int c, int buf) {
        const int k0 = c * 64;
        uint32_t d0 = sb + buf * BUFB;
#pragma unroll
        for (int i = 0; i < 4; i++) {
            int r = r0 + i * 32;
            size_t goff = (size_t)r * D_MODEL + k0 + cc * 8;
            uint32_t soff = (uint32_t)(r * ROWB + cc * 16);
            CP_ASYNC16(d0 + 0 * TILEB + soff, ah_src + goff);
            CP_ASYNC16(d0 + 1 * TILEB + soff, al_src + goff);
            CP_ASYNC16(d0 + 2 * TILEB + soff, bh_src + goff);
            CP_ASYNC16(d0 + 3 * TILEB + soff, bl_src + goff);
        }
    };

    load_chunk(0, 0);
    CP_COMMIT;

    for (int c = 0; c < 64; c++) {
        const int buf = c & 1;
        if (c < 63) {
            load_chunk(c + 1, buf ^ 1);
            CP_COMMIT;
            CP_WAIT(1);
        } else {
            CP_WAIT(0);
        }
        __syncthreads();

        const uint32_t bbase = sb + buf * BUFB;
        const uint32_t aHi = bbase;
        const uint32_t aLo = bbase + TILEB;
        const uint32_t bHi = bbase + 2 * TILEB;
        const uint32_t bLo = bbase + 3 * TILEB;

#pragma unroll 1
        for (int ks = 0; ks < 4; ks++) {
            const uint32_t ko = (uint32_t)(ks * 32);
            uint32_t ahf[2][4], alf[2][4];
#pragma unroll
            for (int mf = 0; mf < 2; mf++) {
                uint32_t mo = (uint32_t)((warpM * 32 + mf * 16) * ROWB) + ko + laneA;
                ldm_x4(ahf[mf], aHi + mo);
                ldm_x4(alf[mf], aLo + mo);
            }
            uint32_t bhf[4][4], blf[4][4];
#pragma unroll
            for (int j = 0; j < 4; j++) {
                uint32_t no = (uint32_t)((warpN * 64 + j * 16) * ROWB) + ko + laneB;
                ldm_x4(bhf[j], bHi + no);
                ldm_x4(blf[j], bLo + no);
            }
#pragma unroll
            for (int mf = 0; mf < 2; mf++)
#pragma unroll
                for (int nf = 0; nf < 8; nf++) {
                    uint32_t b0 = bhf[nf >> 1][(nf & 1) * 2];
                    uint32_t b1 = bhf[nf >> 1][(nf & 1) * 2 + 1];
                    mma16816(acc[mf][nf], ahf[mf], b0, b1);       // hh
                    uint32_t c0 = blf[nf >> 1][(nf & 1) * 2];
                    uint32_t c1 = blf[nf >> 1][(nf & 1) * 2 + 1];
                    mma16816(acc[mf][nf], ahf[mf], c0, c1);       // hl
                    mma16816(acc[mf][nf], alf[mf], b0, b1);       // lh
                }
        }
        __syncthreads();
    }

    __nv_bfloat16 *dh, *dl;
    if (mz == 0)      { dh = g_qh; dl = g_ql; }
    else if (mz == 1) { dh = g_kh; dl = g_kl; }
    else              { dh = g_vh; dl = g_vl; }

    const int qr = lane >> 2;
    const int qc = 2 * (lane & 3);
    const float qscale = 0.08838834764831845f;  // 1/sqrt(128)

    float theta_nf[8];
#pragma unroll
    for (int nf = 0; nf < 8; nf++) {
        int p = warpN * 32 + nf * 4 + (lane & 3);
        theta_nf[nf] = (float)exp(-0.28782313662425574 * (double)p); // ln(1e4)/32
    }

#pragma unroll
    for (int mf = 0; mf < 2; mf++) {
#pragma unroll
        for (int nf = 0; nf < 8; nf++) {
            int row = warpM * 32 + mf * 16 + qr;
            int col = warpN * 64 + nf * 8 + qc;
            size_t mg0 = (size_t)mt * 128 + row;
            size_t mg1 = mg0 + 8;
            float x0 = acc[mf][nf][0], x1 = acc[mf][nf][1];
            float y0 = acc[mf][nf][2], y1 = acc[mf][nf][3];
            if (mz < 2) {
                float th = theta_nf[nf];
                float sn, cs;
                sincosf((float)(int)(mg0 & (SEQ - 1)) * th, &sn, &cs);
                float t0 = x0 * cs - x1 * sn;
                x1 = x1 * cs + x0 * sn; x0 = t0;
                sincosf((float)(int)(mg1 & (SEQ - 1)) * th, &sn, &cs);
                float t1 = y0 * cs - y1 * sn;
                y1 = y1 * cs + y0 * sn; y0 = t1;
            }
            if (mz == 0) { x0 *= qscale; x1 *= qscale; y0 *= qscale; y1 *= qscale; }
            uint32_t h, l;
            split2(x0, x1, h, l);
            *(uint32_t*)&dh[mg0 * HEAD + col] = h;
            *(uint32_t*)&dl[mg0 * HEAD + col] = l;
            split2(y0, y1, h, l);
            *(uint32_t*)&dh[mg1 * HEAD + col] = h;
            *(uint32_t*)&dl[mg1 * HEAD + col] = l;
        }
    }
}

// ===========================================================================
// Kernel 2: split-K causal flash attention (bf16 mma 3-term).
// grid = 288 items; item = (batch, 128-row q-tile, chunk of <=8 k-tiles),
// enumerated qt-descending (big chunks first). block = 256 (8 warps).
// Writes unnormalized partial (o, m, l); merge kernel combines.
// ===========================================================================
#define RB 272
#define ARRB (64 * RB)                  // 17408 (one 64-key bf16 array)
#define QARRB (128 * RB)                // 34816
#define STAGEB (4 * ARRB)               // 69632
#define QH_OFF 0
#define QL_OFF QARRB
#define ST_OFF (2 * QARRB)
#define ATTN_SMEM (ST_OFF + 2 * STAGEB) // 208896
#define CHUNK 8

__global__ __launch_bounds__(256, 1) void attn_kernel()
{
    extern __shared__ __align__(16) char smem[];
    const uint32_t sb = smem_to_u32(smem);
    const int tid = threadIdx.x;
    const int wid = tid >> 5;
    const int lane = tid & 31;

    const int item = blockIdx.x;
    const int b = item / IPB;
    const int it = item - b * IPB;
    int qt = 0, ci = 0, acc = 0;
    for (int q = 31; q >= 0; q--) {          // qt-descending enumeration
        int n = (q + 4) >> 2;                // ceil((q+1)/4) chunks
        if (it < acc + n) { qt = q; ci = it - acc; break; }
        acc += n;
    }
    const int qbase = qt * 128;
    const int kt0 = ci * CHUNK;
    const int ktend = min(kt0 + CHUNK, 2 * qt + 2);

    const uint32_t laneA = (uint32_t)((lane & 15) * RB + ((lane & 16) ? 16 : 0));
    const uint32_t laneB = (uint32_t)(((lane & 7) + ((lane & 16) ? 8 : 0)) * RB
                                      + ((lane & 8) ? 16 : 0));

    // ---- issue Q loads (group 0): 128 rows ----
    {
        const __nv_bfloat16* qh = g_qh + ((size_t)b * SEQ + qbase) * HEAD;
        const __nv_bfloat16* ql = g_ql + ((size_t)b * SEQ + qbase) * HEAD;
#pragma unroll
        for (int i = 0; i < 8; i++) {
            int idx = i * 256 + tid;
            int row = idx >> 4, c = idx & 15;
            uint32_t doff = (uint32_t)(row * RB + c * 16);
            size_t goff = (size_t)row * HEAD + c * 8;
            CP_ASYNC16(sb + QH_OFF + doff, qh + goff);
            CP_ASYNC16(sb + QL_OFF + doff, ql + goff);
        }
        CP_COMMIT;
    }

    auto issue = [&](int kt2, int st2) {
        const size_t gof = ((size_t)b * SEQ + kt2 * 64) * HEAD;
        const __nv_bfloat16* s0 = g_kh + gof;
        const __nv_bfloat16* s1 = g_kl + gof;
        const __nv_bfloat16* s2 = g_vh + gof;
        const __nv_bfloat16* s3 = g_vl + gof;
        const uint32_t d = sb + ST_OFF + st2 * STAGEB;
#pragma unroll
        for (int i = 0; i < 4; i++) {
            int idx = i * 256 + tid;
            int row = idx >> 4, c = idx & 15;
            uint32_t doff = (uint32_t)(row * RB + c * 16);
            size_t goff = (size_t)row * HEAD + c * 8;
            CP_ASYNC16(d + 0 * ARRB + doff, s0 + goff);
            CP_ASYNC16(d + 1 * ARRB + doff, s1 + goff);
            CP_ASYNC16(d + 2 * ARRB + doff, s2 + goff);
            CP_ASYNC16(d + 3 * ARRB + doff, s3 + goff);
        }
    };

    issue(kt0, 0);
    CP_COMMIT;
    CP_WAIT(1);       // Q done
    __syncthreads();

    // ---- persistent Q fragments (warp w -> rows 16w..16w+15) ----
    uint32_t Qhf[8][4], Qlf[8][4];
#pragma unroll
    for (int ks = 0; ks < 8; ks++) {
        uint32_t mo = (uint32_t)((16 * wid) * RB + ks * 32) + laneA;
        ldm_x4(Qhf[ks], sb + QH_OFF + mo);
        ldm_x4(Qlf[ks], sb + QL_OFF + mo);
    }

    float o[16][4];
#pragma unroll
    for (int j = 0; j < 16; j++)
#pragma unroll
        for (int e = 0; e < 4; e++) o[j][e] = 0.f;
    float mA = -1e30f, mB = -1e30f, lA = 0.f, lB = 0.f;

    const int rl0 = 16 * wid + (lane >> 2);      // local q row (and +8)
    const int rgA = qbase + rl0;

    for (int kt = kt0; kt < ktend; kt++) {
        const int st = (kt - kt0) & 1;
        if (kt + 1 < ktend) {
            issue(kt + 1, st ^ 1);
            CP_COMMIT;
            CP_WAIT(1);
        } else {
            CP_WAIT(0);
        }
        __syncthreads();

        const uint32_t kh = sb + ST_OFF + st * STAGEB;
        const uint32_t kl = kh + ARRB;
        const uint32_t vh = kh + 2 * ARRB;
        const uint32_t vl = kh + 3 * ARRB;

        // ---- S = Q K^T (3 terms) ----
        float sacc[8][4];
#pragma unroll
        for (int j = 0; j < 8; j++)
#pragma unroll
            for (int e = 0; e < 4; e++) sacc[j][e] = 0.f;

#pragma unroll 1
        for (int g = 0; g < 4; g++) {
            const uint32_t gb = (uint32_t)((16 * g) * RB) + laneB;
#pragma unroll
            for (int ks = 0; ks < 8; ks++) {
                uint32_t kf[4], lf[4];
                ldm_x4(kf, kh + gb + ks * 32);
                ldm_x4(lf, kl + gb + ks * 32);
                mma16816(sacc[2 * g],     Qhf[ks], kf[0], kf[1]);
                mma16816(sacc[2 * g + 1], Qhf[ks], kf[2], kf[3]);
                mma16816(sacc[2 * g],     Qlf[ks], kf[0], kf[1]);
                mma16816(sacc[2 * g + 1], Qlf[ks], kf[2], kf[3]);
                mma16816(sacc[2 * g],     Qhf[ks], lf[0], lf[1]);
                mma16816(sacc[2 * g + 1], Qhf[ks], lf[2], lf[3]);
            }
        }

        // ---- causal mask (tiles overlapping the diagonal) ----
        if (kt >= 2 * qt) {
            const int cbase = kt * 64 + 2 * (lane & 3);
#pragma unroll
            for (int j = 0; j < 8; j++) {
                int col = cbase + 8 * j;
                if (col > rgA)     sacc[j][0] = -1e30f;
                if (col + 1 > rgA) sacc[j][1] = -1e30f;
                if (col > rgA + 8)     sacc[j][2] = -1e30f;
                if (col + 1 > rgA + 8) sacc[j][3] = -1e30f;
            }
        }

        // ---- online softmax ----
        float mxA = -1e30f, mxB = -1e30f;
#pragma unroll
        for (int j = 0; j < 8; j++) {
            mxA = fmaxf(mxA, fmaxf(sacc[j][0], sacc[j][1]));
            mxB = fmaxf(mxB, fmaxf(sacc[j][2], sacc[j][3]));
        }
        mxA = fmaxf(mxA, __shfl_xor_sync(0xffffffffu, mxA, 1));
        mxA = fmaxf(mxA, __shfl_xor_sync(0xffffffffu, mxA, 2));
        mxB = fmaxf(mxB, __shfl_xor_sync(0xffffffffu, mxB, 1));
        mxB = fmaxf(mxB, __shfl_xor_sync(0xffffffffu, mxB, 2));

        float mAn = fmaxf(mA, mxA), mBn = fmaxf(mB, mxB);
        float alphaA = __expf(mA - mAn), alphaB = __expf(mB - mBn);
        float sA = 0.f, sB = 0.f;
#pragma unroll
        for (int j = 0; j < 8; j++) {
            sacc[j][0] = __expf(sacc[j][0] - mAn);
            sacc[j][1] = __expf(sacc[j][1] - mAn);
            sacc[j][2] = __expf(sacc[j][2] - mBn);
            sacc[j][3] = __expf(sacc[j][3] - mBn);
            sA += sacc[j][0] + sacc[j][1];
            sB += sacc[j][2] + sacc[j][3];
        }
        sA += __shfl_xor_sync(0xffffffffu, sA, 1);
        sA += __shfl_xor_sync(0xffffffffu, sA, 2);
        sB += __shfl_xor_sync(0xffffffffu, sB, 1);
        sB += __shfl_xor_sync(0xffffffffu, sB, 2);
        lA = lA * alphaA + sA;
        lB = lB * alphaB + sB;
        mA = mAn; mB = mBn;
#pragma unroll
        for (int j = 0; j < 16; j++) {
            o[j][0] *= alphaA; o[j][1] *= alphaA;
            o[j][2] *= alphaB; o[j][3] *= alphaB;
        }

        // ---- O += P V (3 terms; P split exactly) ----
#pragma unroll 1
        for (int t = 0; t < 4; t++) {
            uint32_t aH[4], aL[4];
            split2(sacc[2 * t][0],     sacc[2 * t][1],     aH[0], aL[0]);
            split2(sacc[2 * t][2],     sacc[2 * t][3],     aH[1], aL[1]);
            split2(sacc[2 * t + 1][0], sacc[2 * t + 1][1], aH[2], aL[2]);
            split2(sacc[2 * t + 1][2], sacc[2 * t + 1][3], aH[3], aL[3]);
            const uint32_t tb = (uint32_t)((16 * t) * RB) + laneA;
#pragma unroll
            for (int ng = 0; ng < 8; ng++) {
                uint32_t vf[4], wf[4];
                ldm_x4_t(vf, vh + tb + ng * 32);
                ldm_x4_t(wf, vl + tb + ng * 32);
                mma16816(o[2 * ng],     aH, vf[0], vf[1]);
                mma16816(o[2 * ng + 1], aH, vf[2], vf[3]);
                mma16816(o[2 * ng],     aL, vf[0], vf[1]);
                mma16816(o[2 * ng + 1], aL, vf[2], vf[3]);
                mma16816(o[2 * ng],     aH, wf[0], wf[1]);
                mma16816(o[2 * ng + 1], aH, wf[2], wf[3]);
            }
        }
        __syncthreads();
    }

    // ---- write unnormalized partials ----
    float* po = g_po + (size_t)item * (128 * 128);
#pragma unroll
    for (int j = 0; j < 16; j++) {
        int col = 8 * j + 2 * (lane & 3);
        *(float2*)&po[rl0 * 128 + col]       = make_float2(o[j][0], o[j][1]);
        *(float2*)&po[(rl0 + 8) * 128 + col] = make_float2(o[j][2], o[j][3]);
    }
    if ((lane & 3) == 0) {
        g_pm[item * 128 + rl0]     = mA;
        g_pm[item * 128 + rl0 + 8] = mB;
        g_pl[item * 128 + rl0]     = lA;
        g_pl[item * 128 + rl0 + 8] = lB;
    }
}

// ===========================================================================
// Kernel 3: merge partials -> final output. grid = (32 qt, 2 b), block 256.
// ===========================================================================
__global__ __launch_bounds__(256) void merge_kernel(float* __restrict__ out)
{
    const int qt = blockIdx.x;
    const int b = blockIdx.y;
    int base = b * IPB;
    for (int q = 31; q > qt; q--) base += (q + 4) >> 2;
    const int n = (qt + 4) >> 2;

    const int tid = threadIdx.x;
    const int row = tid >> 1;
    const int c0 = (tid & 1) * 64;

    float m[8], w[8];
    float M = -1e30f;
    for (int i = 0; i < n; i++) {
        m[i] = g_pm[(base + i) * 128 + row];
        M = fmaxf(M, m[i]);
    }
    float L = 0.f;
    for (int i = 0; i < n; i++) {
        w[i] = __expf(m[i] - M) ;
        L += w[i] * g_pl[(base + i) * 128 + row];
    }
    const float invL = 1.f / L;
    for (int i = 0; i < n; i++) w[i] *= invL;

    float* orow = out + (((size_t)b * SEQ) + qt * 128 + row) * HEAD + c0;
#pragma unroll 4
    for (int c = 0; c < 64; c += 4) {
        float4 a = make_float4(0.f, 0.f, 0.f, 0.f);
        for (int i = 0; i < n; i++) {
            const float4 p = *(const float4*)&g_po[
                (size_t)(base + i) * (128 * 128) + row * 128 + c0 + c];
            a.x += w[i] * p.x; a.y += w[i] * p.y;
            a.z += w[i] * p.z; a.w += w[i] * p.w;
        }
        *(float4*)&orow[c] = a;
    }
}

extern "C" void kernel_launch(void* const* d_in, const int* in_sizes, int n_in,
                              void* d_out, int out_size)
{
    const float* x  = (const float*)d_in[0];
    const float* Wq = (const float*)d_in[1];
    const float* Wk = (const float*)d_in[2];
    const float* Wv = (const float*)d_in[3];
    float* out = (float*)d_out;

    cudaFuncSetAttribute((const void*)proj_mma_kernel,
                         cudaFuncAttributeMaxDynamicSharedMemorySize, GEMM_SMEM);
    cudaFuncSetAttribute((const void*)attn_kernel,
                         cudaFuncAttributeMaxDynamicSharedMemorySize, ATTN_SMEM);

    conv_kernel<<<CONV_BLOCKS, 256>>>(x, Wq, Wk, Wv);
    proj_mma_kernel<<<dim3(3, 64), 256, GEMM_SMEM>>>();
    attn_kernel<<<NITEMS, 256, ATTN_SMEM>>>();
    merge_kernel<<<dim3(32, BATCH), 256>>>(out);
}

// round 17
// speedup vs baseline: 4.5859x; 1.2527x over previous
#include <cuda_runtime.h>
#include <cuda_bf16.h>
#include <math.h>
#include <stdint.h>

#define D_MODEL 4096
#define HEAD 128
#define SEQ 4096
#define BATCH 2

// bf16 hi/lo split operands (allocation-free rule: static __device__ arrays)
__device__ __align__(16) __nv_bfloat16 g_xh[BATCH * SEQ * D_MODEL];
__device__ __align__(16) __nv_bfloat16 g_xl[BATCH * SEQ * D_MODEL];
__device__ __align__(16) __nv_bfloat16 g_wh[3 * HEAD * D_MODEL];
__device__ __align__(16) __nv_bfloat16 g_wl[3 * HEAD * D_MODEL];

// q/k/v as bf16 hi/lo (q pre-scaled by 1/sqrt(128))
__device__ __align__(16) __nv_bfloat16 g_qh[BATCH * SEQ * HEAD];
__device__ __align__(16) __nv_bfloat16 g_ql[BATCH * SEQ * HEAD];
__device__ __align__(16) __nv_bfloat16 g_kh[BATCH * SEQ * HEAD];
__device__ __align__(16) __nv_bfloat16 g_kl[BATCH * SEQ * HEAD];
__device__ __align__(16) __nv_bfloat16 g_vh[BATCH * SEQ * HEAD];
__device__ __align__(16) __nv_bfloat16 g_vl[BATCH * SEQ * HEAD];

// proj split-K partials: [mz][mt][piece][128*128] fp32
#define KPIECES 3
__device__ float g_pp[3 * 64 * KPIECES * 128 * 128];

// split-K attention partials
#define IPB 144                       // items per batch (sum ceil((qt+1)/4), qt<32)
#define NITEMS (2 * IPB)              // 288
__device__ float g_po[NITEMS * 128 * 128];   // unnormalized partial O
__device__ float g_pm[NITEMS * 128];         // row max
__device__ float g_pl[NITEMS * 128];         // row sum

__device__ __forceinline__ uint32_t smem_to_u32(const void* smem_ptr) {
    uint32_t addr;
    asm("{ .reg .u64 tmp; cvta.to.shared.u64 tmp, %1; cvt.u32.u64 %0, tmp; }"
        : "=r"(addr) : "l"(smem_ptr));
    return addr;
}

#define CP_ASYNC16(dst, src) \
    asm volatile("cp.async.cg.shared.global [%0], [%1], 16;" \
                 :: "r"(dst), "l"(src) : "memory")
#define CP_COMMIT asm volatile("cp.async.commit_group;" ::: "memory")
#define CP_WAIT(n) asm volatile("cp.async.wait_group %0;" :: "n"(n) : "memory")

__device__ __forceinline__ void ldm_x4(uint32_t* r, uint32_t addr) {
    asm volatile("ldmatrix.sync.aligned.m8n8.x4.shared.b16 {%0,%1,%2,%3}, [%4];"
                 : "=r"(r[0]), "=r"(r[1]), "=r"(r[2]), "=r"(r[3]) : "r"(addr));
}
__device__ __forceinline__ void ldm_x4_t(uint32_t* r, uint32_t addr) {
    asm volatile("ldmatrix.sync.aligned.m8n8.x4.trans.shared.b16 {%0,%1,%2,%3}, [%4];"
                 : "=r"(r[0]), "=r"(r[1]), "=r"(r[2]), "=r"(r[3]) : "r"(addr));
}

__device__ __forceinline__ void mma16816(float* c, const uint32_t* a,
                                         uint32_t b0, uint32_t b1) {
    asm volatile(
        "mma.sync.aligned.m16n8k16.row.col.f32.bf16.bf16.f32 "
        "{%0,%1,%2,%3}, {%4,%5,%6,%7}, {%8,%9}, {%0,%1,%2,%3};"
        : "+f"(c[0]), "+f"(c[1]), "+f"(c[2]), "+f"(c[3])
        : "r"(a[0]), "r"(a[1]), "r"(a[2]), "r"(a[3]), "r"(b0), "r"(b1));
}

__device__ __forceinline__ void split2(float a, float b, uint32_t& h, uint32_t& l) {
    __nv_bfloat162 hh, ll;
    hh.x = __float2bfloat16_rn(a);
    hh.y = __float2bfloat16_rn(b);
    ll.x = __float2bfloat16_rn(a - __bfloat162float(hh.x));
    ll.y = __float2bfloat16_rn(b - __bfloat162float(hh.y));
    h = *(uint32_t*)&hh;
    l = *(uint32_t*)&ll;
}

// ===========================================================================
// Kernel 0: fp32 -> bf16 hi/lo split conversion for x and Wq/Wk/Wv.
// ===========================================================================
#define N4X (BATCH * SEQ * D_MODEL / 4)
#define N4W_PER (HEAD * D_MODEL / 4)
#define N4TOT (N4X + 3 * N4W_PER)
#define CONV_BLOCKS (N4TOT / 256)

__global__ __launch_bounds__(256) void conv_kernel(
    const float* __restrict__ x, const float* __restrict__ Wq,
    const float* __restrict__ Wk, const float* __restrict__ Wv)
{
    size_t i = (size_t)blockIdx.x * 256 + threadIdx.x;
    float4 v;
    __nv_bfloat16 *dh, *dl;
    if (i < N4X) {
        v = ((const float4*)x)[i];
        dh = g_xh + i * 4;
        dl = g_xl + i * 4;
    } else {
        size_t j = i - N4X;
        int mz = (int)(j / N4W_PER);
        size_t wj = j - (size_t)mz * N4W_PER;
        const float* W = (mz == 0) ? Wq : (mz == 1) ? Wk : Wv;
        v = ((const float4*)W)[wj];
        dh = g_wh + ((size_t)mz * N4W_PER + wj) * 4;
        dl = g_wl + ((size_t)mz * N4W_PER + wj) * 4;
    }
    uint32_t h01, h23, l01, l23;
    split2(v.x, v.y, h01, l01);
    split2(v.z, v.w, h23, l23);
    *(uint2*)dh = make_uint2(h01, h23);
    *(uint2*)dl = make_uint2(l01, l23);
}

// ===========================================================================
// Kernel 1a: QKV projection partials (bf16 mma 3-term, split-K over 3 pieces).
// grid = (3 {q,k,v}, 64 m-tiles, 3 pieces), block = 256 (8 warps, 4m x 2n).
// Piece chunk ranges: [0,22), [22,43), [43,64).
// ===========================================================================
#define ROWB 144
#define TILEB (128 * ROWB)
#define BUFB (4 * TILEB)
#define GEMM_SMEM (2 * BUFB)

__global__ __launch_bounds__(256) void proj_partial_kernel()
{
    extern __shared__ __align__(16) char smem[];
    const int tid = threadIdx.x;
    const int wid = tid >> 5;
    const int lane = tid & 31;
    const int warpM = wid & 3;
    const int warpN = wid >> 2;
    const int mz = blockIdx.x;
    const int mt = blockIdx.y;
    const int piece = blockIdx.z;

    const int cs = (piece == 0) ? 0 : (piece == 1) ? 22 : 43;
    const int ce = (piece == 0) ? 22 : (piece == 1) ? 43 : 64;

    const uint32_t sb = smem_to_u32(smem);

    const __nv_bfloat16* __restrict__ ah_src = g_xh + (size_t)mt * 128 * D_MODEL;
    const __nv_bfloat16* __restrict__ al_src = g_xl + (size_t)mt * 128 * D_MODEL;
    const __nv_bfloat16* __restrict__ bh_src = g_wh + (size_t)mz * HEAD * D_MODEL;
    const __nv_bfloat16* __restrict__ bl_src = g_wl + (size_t)mz * HEAD * D_MODEL;

    const int cc = tid & 7;
    const int r0 = tid >> 3;

    const uint32_t laneA = (uint32_t)((lane & 15) * ROWB + ((lane & 16) ? 16 : 0));
    const uint32_t laneB = (uint32_t)(((lane & 7) + ((lane & 16) ? 8 : 0)) * ROWB
                                      + ((lane & 8) ? 16 : 0));

    float acc[2][8][4];
#pragma unroll
    for (int mf = 0; mf < 2; mf++)
#pragma unroll
        for (int nf = 0; nf < 8; nf++)
#pragma unroll
            for (int e = 0; e < 4; e++) acc[mf][nf][e] = 0.f;

    auto load_chunk = [&](int c, int buf) {
        const int k0 = c * 64;
        uint32_t d0 = sb + buf * BUFB;
#pragma unroll
        for (int i = 0; i < 4; i++) {
            int r = r0 + i * 32;
            size_t goff = (size_t)r * D_MODEL + k0 + cc * 8;
            uint32_t soff = (uint32_t)(r * ROWB + cc * 16);
            CP_ASYNC16(d0 + 0 * TILEB + soff, ah_src + goff);
            CP_ASYNC16(d0 + 1 * TILEB + soff, al_src + goff);
            CP_ASYNC16(d0 + 2 * TILEB + soff, bh_src + goff);
            CP_ASYNC16(d0 + 3 * TILEB + soff, bl_src + goff);
        }
    };

    load_chunk(cs, 0);
    CP_COMMIT;

    for (int c = cs; c < ce; c++) {
        const int buf = (c - cs) & 1;
        if (c + 1 < ce) {
            load_chunk(c + 1, buf ^ 1);
            CP_COMMIT;
            CP_WAIT(1);
        } else {
            CP_WAIT(0);
        }
        __syncthreads();

        const uint32_t bbase = sb + buf * BUFB;
        const uint32_t aHi = bbase;
        const uint32_t aLo = bbase + TILEB;
        const uint32_t bHi = bbase + 2 * TILEB;
        const uint32_t bLo = bbase + 3 * TILEB;

#pragma unroll 1
        for (int ks = 0; ks < 4; ks++) {
            const uint32_t ko = (uint32_t)(ks * 32);
            uint32_t ahf[2][4], alf[2][4];
#pragma unroll
            for (int mf = 0; mf < 2; mf++) {
                uint32_t mo = (uint32_t)((warpM * 32 + mf * 16) * ROWB) + ko + laneA;
                ldm_x4(ahf[mf], aHi + mo);
                ldm_x4(alf[mf], aLo + mo);
            }
            uint32_t bhf[4][4], blf[4][4];
#pragma unroll
            for (int j = 0; j < 4; j++) {
                uint32_t no = (uint32_t)((warpN * 64 + j * 16) * ROWB) + ko + laneB;
                ldm_x4(bhf[j], bHi + no);
                ldm_x4(blf[j], bLo + no);
            }
#pragma unroll
            for (int mf = 0; mf < 2; mf++)
#pragma unroll
                for (int nf = 0; nf < 8; nf++) {
                    uint32_t b0 = bhf[nf >> 1][(nf & 1) * 2];
                    uint32_t b1 = bhf[nf >> 1][(nf & 1) * 2 + 1];
                    mma16816(acc[mf][nf], ahf[mf], b0, b1);       // hh
                    uint32_t c0 = blf[nf >> 1][(nf & 1) * 2];
                    uint32_t c1 = blf[nf >> 1][(nf & 1) * 2 + 1];
                    mma16816(acc[mf][nf], ahf[mf], c0, c1);       // hl
                    mma16816(acc[mf][nf], alf[mf], b0, b1);       // lh
                }
        }
        __syncthreads();
    }

    // ---- write fp32 partial tile ----
    float* __restrict__ pp = g_pp +
        (size_t)(((mz * 64 + mt) * KPIECES) + piece) * (128 * 128);
    const int qr = lane >> 2;
    const int qc = 2 * (lane & 3);
#pragma unroll
    for (int mf = 0; mf < 2; mf++) {
#pragma unroll
        for (int nf = 0; nf < 8; nf++) {
            int row = warpM * 32 + mf * 16 + qr;
            int col = warpN * 64 + nf * 8 + qc;
            *(float2*)&pp[row * 128 + col] =
                make_float2(acc[mf][nf][0], acc[mf][nf][1]);
            *(float2*)&pp[(row + 8) * 128 + col] =
                make_float2(acc[mf][nf][2], acc[mf][nf][3]);
        }
    }
}

// ===========================================================================
// Kernel 1b: proj epilogue: sum 3 partials + RoPE (q,k) + qscale + bf16 split.
// grid = (3, 64), block = 256. Thread: one row-half (64 cols).
// ===========================================================================
__global__ __launch_bounds__(256) void proj_epi_kernel()
{
    __shared__ float s_theta[64];
    const int mz = blockIdx.x;
    const int mt = blockIdx.y;
    const int tid = threadIdx.x;

    if (tid < 64)
        s_theta[tid] = (float)exp(-0.28782313662425574 * (double)tid); // ln(1e4)/32
    __syncthreads();

    const int row = tid >> 1;
    const int c0 = (tid & 1) * 64;

    const size_t pb = (size_t)((mz * 64 + mt) * KPIECES) * (128 * 128)
                      + (size_t)row * 128 + c0;
    const float* __restrict__ p0 = g_pp + pb;
    const float* __restrict__ p1 = p0 + 128 * 128;
    const float* __restrict__ p2 = p1 + 128 * 128;

    __nv_bfloat16 *dh, *dl;
    if (mz == 0)      { dh = g_qh; dl = g_ql; }
    else if (mz == 1) { dh = g_kh; dl = g_kl; }
    else              { dh = g_vh; dl = g_vl; }

    const size_t mg = (size_t)mt * 128 + row;          // global row over B*S
    const int s = (int)(mg & (SEQ - 1));
    const float sf = (float)s;
    const float qscale = 0.08838834764831845f;         // 1/sqrt(128)

#pragma unroll 4
    for (int j = 0; j < 16; j++) {
        const int c = j * 4;
        float4 a0 = *(const float4*)&p0[c];
        float4 a1 = *(const float4*)&p1[c];
        float4 a2 = *(const float4*)&p2[c];
        float x0 = a0.x + a1.x + a2.x;
        float x1 = a0.y + a1.y + a2.y;
        float y0 = a0.z + a1.z + a2.z;
        float y1 = a0.w + a1.w + a2.w;
        if (mz < 2) {
            float sn, cs;
            sincosf(sf * s_theta[(c0 + c) >> 1], &sn, &cs);
            float t = x0 * cs - x1 * sn;
            x1 = x1 * cs + x0 * sn; x0 = t;
            sincosf(sf * s_theta[((c0 + c) >> 1) + 1], &sn, &cs);
            t = y0 * cs - y1 * sn;
            y1 = y1 * cs + y0 * sn; y0 = t;
        } else if (mz == 0) {
            // unreachable; kept for symmetry
        }
        if (mz == 0) { x0 *= qscale; x1 *= qscale; y0 *= qscale; y1 *= qscale; }
        uint32_t h0, l0, h1, l1;
        split2(x0, x1, h0, l0);
        split2(y0, y1, h1, l1);
        *(uint2*)&dh[mg * HEAD + c0 + c] = make_uint2(h0, h1);
        *(uint2*)&dl[mg * HEAD + c0 + c] = make_uint2(l0, l1);
    }
}

// ===========================================================================
// Kernel 2: split-K causal flash attention (bf16 mma 3-term).
// grid = 288 items; item = (batch, 128-row q-tile, chunk of <=8 k-tiles),
// enumerated qt-descending (big chunks first). block = 256 (8 warps).
// ===========================================================================
#define RB 272
#define ARRB (64 * RB)                  // 17408 (one 64-key bf16 array)
#define QARRB (128 * RB)                // 34816
#define STAGEB (4 * ARRB)               // 69632
#define QH_OFF 0
#define QL_OFF QARRB
#define ST_OFF (2 * QARRB)
#define ATTN_SMEM (ST_OFF + 2 * STAGEB) // 208896
#define CHUNK 8

__global__ __launch_bounds__(256, 1) void attn_kernel()
{
    extern __shared__ __align__(16) char smem[];
    const uint32_t sb = smem_to_u32(smem);
    const int tid = threadIdx.x;
    const int wid = tid >> 5;
    const int lane = tid & 31;

    const int item = blockIdx.x;
    const int b = item / IPB;
    const int it = item - b * IPB;
    int qt = 0, ci = 0, acc = 0;
    for (int q = 31; q >= 0; q--) {          // qt-descending enumeration
        int n = (q + 4) >> 2;                // ceil((q+1)/4) chunks
        if (it < acc + n) { qt = q; ci = it - acc; break; }
        acc += n;
    }
    const int qbase = qt * 128;
    const int kt0 = ci * CHUNK;
    const int ktend = min(kt0 + CHUNK, 2 * qt + 2);

    const uint32_t laneA = (uint32_t)((lane & 15) * RB + ((lane & 16) ? 16 : 0));
    const uint32_t laneB = (uint32_t)(((lane & 7) + ((lane & 16) ? 8 : 0)) * RB
                                      + ((lane & 8) ? 16 : 0));

    // ---- issue Q loads (group 0): 128 rows ----
    {
        const __nv_bfloat16* qh = g_qh + ((size_t)b * SEQ + qbase) * HEAD;
        const __nv_bfloat16* ql = g_ql + ((size_t)b * SEQ + qbase) * HEAD;
#pragma unroll
        for (int i = 0; i < 8; i++) {
            int idx = i * 256 + tid;
            int row = idx >> 4, c = idx & 15;
            uint32_t doff = (uint32_t)(row * RB + c * 16);
            size_t goff = (size_t)row * HEAD + c * 8;
            CP_ASYNC16(sb + QH_OFF + doff, qh + goff);
            CP_ASYNC16(sb + QL_OFF + doff, ql + goff);
        }
        CP_COMMIT;
    }

    auto issue = [&](int kt2, int st2) {
        const size_t gof = ((size_t)b * SEQ + kt2 * 64) * HEAD;
        const __nv_bfloat16* s0 = g_kh + gof;
        const __nv_bfloat16* s1 = g_kl + gof;
        const __nv_bfloat16* s2 = g_vh + gof;
        const __nv_bfloat16* s3 = g_vl + gof;
        const uint32_t d = sb + ST_OFF + st2 * STAGEB;
#pragma unroll
        for (int i = 0; i < 4; i++) {
            int idx = i * 256 + tid;
            int row = idx >> 4, c = idx & 15;
            uint32_t doff = (uint32_t)(row * RB + c * 16);
            size_t goff = (size_t)row * HEAD + c * 8;
            CP_ASYNC16(d + 0 * ARRB + doff, s0 + goff);
            CP_ASYNC16(d + 1 * ARRB + doff, s1 + goff);
            CP_ASYNC16(d + 2 * ARRB + doff, s2 + goff);
            CP_ASYNC16(d + 3 * ARRB + doff, s3 + goff);
        }
    };

    issue(kt0, 0);
    CP_COMMIT;
    CP_WAIT(1);       // Q done
    __syncthreads();

    // ---- persistent Q fragments (warp w -> rows 16w..16w+15) ----
    uint32_t Qhf[8][4], Qlf[8][4];
#pragma unroll
    for (int ks = 0; ks < 8; ks++) {
        uint32_t mo = (uint32_t)((16 * wid) * RB + ks * 32) + laneA;
        ldm_x4(Qhf[ks], sb + QH_OFF + mo);
        ldm_x4(Qlf[ks], sb + QL_OFF + mo);
    }

    float o[16][4];
#pragma unroll
    for (int j = 0; j < 16; j++)
#pragma unroll
        for (int e = 0; e < 4; e++) o[j][e] = 0.f;
    float mA = -1e30f, mB = -1e30f, lA = 0.f, lB = 0.f;

    const int rl0 = 16 * wid + (lane >> 2);      // local q row (and +8)
    const int rgA = qbase + rl0;

    for (int kt = kt0; kt < ktend; kt++) {
        const int st = (kt - kt0) & 1;
        if (kt + 1 < ktend) {
            issue(kt + 1, st ^ 1);
            CP_COMMIT;
            CP_WAIT(1);
        } else {
            CP_WAIT(0);
        }
        __syncthreads();

        const uint32_t kh = sb + ST_OFF + st * STAGEB;
        const uint32_t kl = kh + ARRB;
        const uint32_t vh = kh + 2 * ARRB;
        const uint32_t vl = kh + 3 * ARRB;

        // ---- S = Q K^T (3 terms) ----
        float sacc[8][4];
#pragma unroll
        for (int j = 0; j < 8; j++)
#pragma unroll
            for (int e = 0; e < 4; e++) sacc[j][e] = 0.f;

#pragma unroll 1
        for (int g = 0; g < 4; g++) {
            const uint32_t gb = (uint32_t)((16 * g) * RB) + laneB;
#pragma unroll
            for (int ks = 0; ks < 8; ks++) {
                uint32_t kf[4], lf[4];
                ldm_x4(kf, kh + gb + ks * 32);
                ldm_x4(lf, kl + gb + ks * 32);
                mma16816(sacc[2 * g],     Qhf[ks], kf[0], kf[1]);
                mma16816(sacc[2 * g + 1], Qhf[ks], kf[2], kf[3]);
                mma16816(sacc[2 * g],     Qlf[ks], kf[0], kf[1]);
                mma16816(sacc[2 * g + 1], Qlf[ks], kf[2], kf[3]);
                mma16816(sacc[2 * g],     Qhf[ks], lf[0], lf[1]);
                mma16816(sacc[2 * g + 1], Qhf[ks], lf[2], lf[3]);
            }
        }

        // ---- causal mask (tiles overlapping the diagonal) ----
        if (kt >= 2 * qt) {
            const int cbase = kt * 64 + 2 * (lane & 3);
#pragma unroll
            for (int j = 0; j < 8; j++) {
                int col = cbase + 8 * j;
                if (col > rgA)     sacc[j][0] = -1e30f;
                if (col + 1 > rgA) sacc[j][1] = -1e30f;
                if (col > rgA + 8)     sacc[j][2] = -1e30f;
                if (col + 1 > rgA + 8) sacc[j][3] = -1e30f;
            }
        }

        // ---- online softmax ----
        float mxA = -1e30f, mxB = -1e30f;
#pragma unroll
        for (int j = 0; j < 8; j++) {
            mxA = fmaxf(mxA, fmaxf(sacc[j][0], sacc[j][1]));
            mxB = fmaxf(mxB, fmaxf(sacc[j][2], sacc[j][3]));
        }
        mxA = fmaxf(mxA, __shfl_xor_sync(0xffffffffu, mxA, 1));
        mxA = fmaxf(mxA, __shfl_xor_sync(0xffffffffu, mxA, 2));
        mxB = fmaxf(mxB, __shfl_xor_sync(0xffffffffu, mxB, 1));
        mxB = fmaxf(mxB, __shfl_xor_sync(0xffffffffu, mxB, 2));

        float mAn = fmaxf(mA, mxA), mBn = fmaxf(mB, mxB);
        float alphaA = __expf(mA - mAn), alphaB = __expf(mB - mBn);
        float sA = 0.f, sB = 0.f;
#pragma unroll
        for (int j = 0; j < 8; j++) {
            sacc[j][0] = __expf(sacc[j][0] - mAn);
            sacc[j][1] = __expf(sacc[j][1] - mAn);
            sacc[j][2] = __expf(sacc[j][2] - mBn);
            sacc[j][3] = __expf(sacc[j][3] - mBn);
            sA += sacc[j][0] + sacc[j][1];
            sB += sacc[j][2] + sacc[j][3];
        }
        sA += __shfl_xor_sync(0xffffffffu, sA, 1);
        sA += __shfl_xor_sync(0xffffffffu, sA, 2);
        sB += __shfl_xor_sync(0xffffffffu, sB, 1);
        sB += __shfl_xor_sync(0xffffffffu, sB, 2);
        lA = lA * alphaA + sA;
        lB = lB * alphaB + sB;
        mA = mAn; mB = mBn;
#pragma unroll
        for (int j = 0; j < 16; j++) {
            o[j][0] *= alphaA; o[j][1] *= alphaA;
            o[j][2] *= alphaB; o[j][3] *= alphaB;
        }

        // ---- O += P V (3 terms; P split exactly) ----
#pragma unroll 1
        for (int t = 0; t < 4; t++) {
            uint32_t aH[4], aL[4];
            split2(sacc[2 * t][0],     sacc[2 * t][1],     aH[0], aL[0]);
            split2(sacc[2 * t][2],     sacc[2 * t][3],     aH[1], aL[1]);
            split2(sacc[2 * t + 1][0], sacc[2 * t + 1][1], aH[2], aL[2]);
            split2(sacc[2 * t + 1][2], sacc[2 * t + 1][3], aH[3], aL[3]);
            const uint32_t tb = (uint32_t)((16 * t) * RB) + laneA;
#pragma unroll
            for (int ng = 0; ng < 8; ng++) {
                uint32_t vf[4], wf[4];
                ldm_x4_t(vf, vh + tb + ng * 32);
                ldm_x4_t(wf, vl + tb + ng * 32);
                mma16816(o[2 * ng],     aH, vf[0], vf[1]);
                mma16816(o[2 * ng + 1], aH, vf[2], vf[3]);
                mma16816(o[2 * ng],     aL, vf[0], vf[1]);
                mma16816(o[2 * ng + 1], aL, vf[2], vf[3]);
                mma16816(o[2 * ng],     aH, wf[0], wf[1]);
                mma16816(o[2 * ng + 1], aH, wf[2], wf[3]);
            }
        }
        __syncthreads();
    }

    // ---- write unnormalized partials ----
    float* po = g_po + (size_t)item * (128 * 128);
#pragma unroll
    for (int j = 0; j < 16; j++) {
        int col = 8 * j + 2 * (lane & 3);
        *(float2*)&po[rl0 * 128 + col]       = make_float2(o[j][0], o[j][1]);
        *(float2*)&po[(rl0 + 8) * 128 + col] = make_float2(o[j][2], o[j][3]);
    }
    if ((lane & 3) == 0) {
        g_pm[item * 128 + rl0]     = mA;
        g_pm[item * 128 + rl0 + 8] = mB;
        g_pl[item * 128 + rl0]     = lA;
        g_pl[item * 128 + rl0 + 8] = lB;
    }
}

// ===========================================================================
// Kernel 3: merge partials -> final output. grid = (32 qt, 2 b, 4 row-groups).
// ===========================================================================
__global__ __launch_bounds__(256) void merge_kernel(float* __restrict__ out)
{
    const int qt = blockIdx.x;
    const int b = blockIdx.y;
    int base = b * IPB;
    for (int q = 31; q > qt; q--) base += (q + 4) >> 2;
    const int n = (qt + 4) >> 2;

    const int tid = threadIdx.x;
    const int row = blockIdx.z * 32 + (tid >> 3);
    const int c0 = (tid & 7) * 16;

    float m[8], w[8];
    float M = -1e30f;
    for (int i = 0; i < n; i++) {
        m[i] = g_pm[(base + i) * 128 + row];
        M = fmaxf(M, m[i]);
    }
    float L = 0.f;
    for (int i = 0; i < n; i++) {
        w[i] = __expf(m[i] - M);
        L += w[i] * g_pl[(base + i) * 128 + row];
    }
    const float invL = 1.f / L;
    for (int i = 0; i < n; i++) w[i] *= invL;

    float* orow = out + (((size_t)b * SEQ) + qt * 128 + row) * HEAD + c0;
#pragma unroll
    for (int c = 0; c < 16; c += 4) {
        float4 a = make_float4(0.f, 0.f, 0.f, 0.f);
        for (int i = 0; i < n; i++) {
            const float4 p = *(const float4*)&g_po[
                (size_t)(base + i) * (128 * 128) + row * 128 + c0 + c];
            a.x += w[i] * p.x; a.y += w[i] * p.y;
            a.z += w[i] * p.z; a.w += w[i] * p.w;
        }
        *(float4*)&orow[c] = a;
    }
}

extern "C" void kernel_launch(void* const* d_in, const int* in_sizes, int n_in,
                              void* d_out, int out_size)
{
    const float* x  = (const float*)d_in[0];
    const float* Wq = (const float*)d_in[1];
    const float* Wk = (const float*)d_in[2];
    const float* Wv = (const float*)d_in[3];
    float* out = (float*)d_out;

    cudaFuncSetAttribute((const void*)proj_partial_kernel,
                         cudaFuncAttributeMaxDynamicSharedMemorySize, GEMM_SMEM);
    cudaFuncSetAttribute((const void*)attn_kernel,
                         cudaFuncAttributeMaxDynamicSharedMemorySize, ATTN_SMEM);

    conv_kernel<<<CONV_BLOCKS, 256>>>(x, Wq, Wk, Wv);
    proj_partial_kernel<<<dim3(3, 64, KPIECES), 256, GEMM_SMEM>>>();
    proj_epi_kernel<<<dim3(3, 64), 256>>>();
    attn_kernel<<<NITEMS, 256, ATTN_SMEM>>>();
    merge_kernel<<<dim3(32, BATCH, 4), 256>>>(out);
}